// round 1
// baseline (speedup 1.0000x reference)
#include <cuda_runtime.h>

// Problem constants
constexpr int BATCH = 8;
constexpr int T = 2048;
constexpr int C = 512;                 // IN_CH = KEY = VAL = 512
constexpr int M_TOT = BATCH * T;       // 16384
constexpr float SCALE = 0.044194173824159216f; // 1/sqrt(512)

// Scratch (device globals: allocation-free rule)
__device__ float g_q[M_TOT * C];
__device__ float g_k[M_TOT * C];
__device__ float g_kT[BATCH * C * T];
__device__ float g_v[M_TOT * C];
__device__ float g_logits[(size_t)BATCH * T * T];   // logits, then probs in-place
__device__ float g_cmax[M_TOT];
__device__ float g_cinv[M_TOT];

// ---------------------------------------------------------------------------
// 128x128x8 SGEMM core: 256 threads, 8x8 accumulator per thread.
// A is [M,K] row-major (lda=K stride), B is [K,N] row-major (ldb=N stride).
// ---------------------------------------------------------------------------
__device__ __forceinline__ void gemm_core(const float* __restrict__ A, int lda,
                                          const float* __restrict__ Bm, int ldb,
                                          int rBase, int cBase, int kEnd,
                                          float acc[8][8])
{
    __shared__ float As[8][128];
    __shared__ float Bs[8][128];
    const int tid  = threadIdx.x;
    const int arow = tid >> 1;          // 0..127
    const int acol = (tid & 1) << 2;    // 0 or 4
    const int brow = tid >> 5;          // 0..7
    const int bcol = (tid & 31) << 2;   // 0..124
    const int ty = tid >> 4;            // 0..15
    const int tx = tid & 15;            // 0..15

    const float* Aptr = A + (size_t)(rBase + arow) * lda + acol;
    const float* Bptr = Bm + (size_t)brow * ldb + cBase + bcol;

    for (int k0 = 0; k0 < kEnd; k0 += 8) {
        float4 a4 = *(const float4*)(Aptr + k0);
        As[acol + 0][arow] = a4.x;
        As[acol + 1][arow] = a4.y;
        As[acol + 2][arow] = a4.z;
        As[acol + 3][arow] = a4.w;
        *(float4*)&Bs[brow][bcol] = *(const float4*)(Bptr + (size_t)k0 * ldb);
        __syncthreads();
#pragma unroll
        for (int kk = 0; kk < 8; ++kk) {
            float ar[8], br[8];
            *(float4*)(ar)     = *(const float4*)&As[kk][ty * 8];
            *(float4*)(ar + 4) = *(const float4*)&As[kk][ty * 8 + 4];
            *(float4*)(br)     = *(const float4*)&Bs[kk][tx * 8];
            *(float4*)(br + 4) = *(const float4*)&Bs[kk][tx * 8 + 4];
#pragma unroll
            for (int i = 0; i < 8; ++i)
#pragma unroll
                for (int j = 0; j < 8; ++j)
                    acc[i][j] = fmaf(ar[i], br[j], acc[i][j]);
        }
        __syncthreads();
    }
}

// ---------------------------------------------------------------------------
// 1. QKV projection: grid.z selects q/k/v. M=16384, N=512, K=512, + bias.
// ---------------------------------------------------------------------------
__global__ __launch_bounds__(256)
void qkv_kernel(const float* __restrict__ x,
                const float* __restrict__ Wq, const float* __restrict__ bq,
                const float* __restrict__ Wk, const float* __restrict__ bk,
                const float* __restrict__ Wv, const float* __restrict__ bv)
{
    const float* W; const float* bias; float* out;
    if (blockIdx.z == 0)      { W = Wq; bias = bq; out = g_q; }
    else if (blockIdx.z == 1) { W = Wk; bias = bk; out = g_k; }
    else                      { W = Wv; bias = bv; out = g_v; }

    const int rBase = blockIdx.y * 128;
    const int cBase = blockIdx.x * 128;
    float acc[8][8] = {};
    gemm_core(x, C, W, C, rBase, cBase, C, acc);

    const int ty = threadIdx.x >> 4, tx = threadIdx.x & 15;
    const int col = cBase + tx * 8;
    float4 bia0 = *(const float4*)&bias[col];
    float4 bia1 = *(const float4*)&bias[col + 4];
#pragma unroll
    for (int i = 0; i < 8; ++i) {
        float* dst = out + (size_t)(rBase + ty * 8 + i) * C + col;
        float4 o0, o1;
        o0.x = acc[i][0] + bia0.x; o0.y = acc[i][1] + bia0.y;
        o0.z = acc[i][2] + bia0.z; o0.w = acc[i][3] + bia0.w;
        o1.x = acc[i][4] + bia1.x; o1.y = acc[i][5] + bia1.y;
        o1.z = acc[i][6] + bia1.z; o1.w = acc[i][7] + bia1.w;
        *(float4*)(dst)     = o0;
        *(float4*)(dst + 4) = o1;
    }
}

// ---------------------------------------------------------------------------
// 2. Transpose k -> kT per batch: [T,C] -> [C,T]
// ---------------------------------------------------------------------------
__global__ void transpose_kernel()
{
    __shared__ float tile[32][33];
    const int b = blockIdx.z;
    const int t0 = blockIdx.x * 32;
    const int c0 = blockIdx.y * 32;
    const float* src = g_k + (size_t)b * T * C;
    float* dst = g_kT + (size_t)b * C * T;
    const int x = threadIdx.x, y = threadIdx.y;
#pragma unroll
    for (int j = 0; j < 32; j += 8)
        tile[y + j][x] = src[(size_t)(t0 + y + j) * C + c0 + x];
    __syncthreads();
#pragma unroll
    for (int j = 0; j < 32; j += 8)
        dst[(size_t)(c0 + y + j) * T + t0 + x] = tile[x][y + j];
}

// ---------------------------------------------------------------------------
// 3. logits[t,s] = (q[t,:] . k[s,:]) / sqrt(K); skip strictly-upper tiles.
// ---------------------------------------------------------------------------
__global__ __launch_bounds__(256)
void logits_kernel()
{
    const int bx = blockIdx.x, by = blockIdx.y, b = blockIdx.z;
    if (bx > by) return;   // whole tile is masked (s > t everywhere)
    const int rBase = by * 128;
    const int cBase = bx * 128;
    const float* A  = g_q  + (size_t)b * T * C;
    const float* Bm = g_kT + (size_t)b * C * T;
    float* Cp = g_logits + (size_t)b * T * T;

    float acc[8][8] = {};
    gemm_core(A, C, Bm, T, rBase, cBase, C, acc);

    const int ty = threadIdx.x >> 4, tx = threadIdx.x & 15;
#pragma unroll
    for (int i = 0; i < 8; ++i) {
        float* dst = Cp + (size_t)(rBase + ty * 8 + i) * T + cBase + tx * 8;
        float4 o0, o1;
        o0.x = acc[i][0] * SCALE; o0.y = acc[i][1] * SCALE;
        o0.z = acc[i][2] * SCALE; o0.w = acc[i][3] * SCALE;
        o1.x = acc[i][4] * SCALE; o1.y = acc[i][5] * SCALE;
        o1.z = acc[i][6] * SCALE; o1.w = acc[i][7] * SCALE;
        *(float4*)(dst)     = o0;
        *(float4*)(dst + 4) = o1;
    }
}

// ---------------------------------------------------------------------------
// 4. Column stats (softmax over QUERY axis t, per key column s): online max/sum
//    over t in [s, T). Stores max and reciprocal of sum.
// ---------------------------------------------------------------------------
__global__ void colstats_kernel()
{
    const int b = blockIdx.y;
    const int s = blockIdx.x * blockDim.x + threadIdx.x;
    const float* L = g_logits + (size_t)b * T * T;
    float m = -1e30f, d = 0.f;
    for (int t = s; t < T; ++t) {
        float l = L[(size_t)t * T + s];
        if (l > m) { d = d * __expf(m - l) + 1.0f; m = l; }
        else       { d += __expf(l - m); }
    }
    g_cmax[b * T + s] = m;
    g_cinv[b * T + s] = 1.0f / d;
}

// ---------------------------------------------------------------------------
// 5. probs in place: p[t,s] = (s<=t) ? exp(l - cmax[s]) * cinv[s] : 0
// ---------------------------------------------------------------------------
__global__ void probs_kernel()
{
    const int b = blockIdx.z, t = blockIdx.y;
    const int s = (blockIdx.x * blockDim.x + threadIdx.x) << 2;
    const size_t base = (size_t)b * T * T + (size_t)t * T + s;
    float4 l  = *(const float4*)&g_logits[base];
    float4 cm = *(const float4*)&g_cmax[b * T + s];
    float4 ci = *(const float4*)&g_cinv[b * T + s];
    float4 p;
    p.x = (s + 0 <= t) ? __expf(l.x - cm.x) * ci.x : 0.f;
    p.y = (s + 1 <= t) ? __expf(l.y - cm.y) * ci.y : 0.f;
    p.z = (s + 2 <= t) ? __expf(l.z - cm.z) * ci.z : 0.f;
    p.w = (s + 3 <= t) ? __expf(l.w - cm.w) * ci.w : 0.f;
    *(float4*)&g_logits[base] = p;
}

// ---------------------------------------------------------------------------
// 6. read = probs @ v, written into out[..., 512:1024] (row stride 1024).
//    k-loop clamped to rBase+128 (probs is 0 above the diagonal).
// ---------------------------------------------------------------------------
__global__ __launch_bounds__(256)
void pv_kernel(float* __restrict__ out)
{
    const int b = blockIdx.z;
    const int rBase = blockIdx.y * 128;
    const int cBase = blockIdx.x * 128;
    const float* A  = g_logits + (size_t)b * T * T;   // probs
    const float* Bm = g_v      + (size_t)b * T * C;

    float acc[8][8] = {};
    gemm_core(A, T, Bm, C, rBase, cBase, rBase + 128, acc);

    const int ty = threadIdx.x >> 4, tx = threadIdx.x & 15;
#pragma unroll
    for (int i = 0; i < 8; ++i) {
        const int t = rBase + ty * 8 + i;
        float* dst = out + ((size_t)(b * T + t) * 1024) + 512 + cBase + tx * 8;
        float4 o0, o1;
        o0.x = acc[i][0]; o0.y = acc[i][1]; o0.z = acc[i][2]; o0.w = acc[i][3];
        o1.x = acc[i][4]; o1.y = acc[i][5]; o1.z = acc[i][6]; o1.w = acc[i][7];
        *(float4*)(dst)     = o0;
        *(float4*)(dst + 4) = o1;
    }
}

// ---------------------------------------------------------------------------
// 7. out[..., 0:512] = x
// ---------------------------------------------------------------------------
__global__ void copyx_kernel(const float* __restrict__ x, float* __restrict__ out)
{
    const int i = blockIdx.x * blockDim.x + threadIdx.x;   // float4 index
    const int row = i >> 7;     // token index (128 float4 per row)
    const int c4  = i & 127;
    ((float4*)out)[(size_t)row * 256 + c4] = ((const float4*)x)[(size_t)row * 128 + c4];
}

// ---------------------------------------------------------------------------
extern "C" void kernel_launch(void* const* d_in, const int* in_sizes, int n_in,
                              void* d_out, int out_size)
{
    const float* x  = (const float*)d_in[0];
    const float* Wq = (const float*)d_in[1];
    const float* bq = (const float*)d_in[2];
    const float* Wk = (const float*)d_in[3];
    const float* bk = (const float*)d_in[4];
    const float* Wv = (const float*)d_in[5];
    const float* bv = (const float*)d_in[6];
    float* out = (float*)d_out;

    qkv_kernel<<<dim3(C / 128, M_TOT / 128, 3), 256>>>(x, Wq, bq, Wk, bk, Wv, bv);
    transpose_kernel<<<dim3(T / 32, C / 32, BATCH), dim3(32, 8)>>>();
    logits_kernel<<<dim3(T / 128, T / 128, BATCH), 256>>>();
    colstats_kernel<<<dim3(T / 128, BATCH), 128>>>();
    probs_kernel<<<dim3(T / 1024, T, BATCH), 256>>>();
    pv_kernel<<<dim3(C / 128, T / 128, BATCH), 256>>>(out);
    copyx_kernel<<<(M_TOT * 128) / 256, 256>>>(x, out);
}

// round 2
// speedup vs baseline: 2.3716x; 2.3716x over previous
#include <cuda_runtime.h>
#include <cstdint>

// Problem constants
constexpr int BATCH = 8;
constexpr int T = 2048;
constexpr int C = 512;                 // IN_CH = KEY = VAL = 512
constexpr int M_TOT = BATCH * T;       // 16384
constexpr float SCALE = 0.044194173824159216f; // 1/sqrt(512)

// Scratch (device globals: allocation-free rule)
__device__ float g_q[M_TOT * C];       // pre-scaled by SCALE
__device__ float g_k[M_TOT * C];
__device__ float g_kT[BATCH * C * T];
__device__ float g_v[M_TOT * C];
__device__ float g_logits[(size_t)BATCH * T * T];   // logits, then probs in-place
__device__ float g_cmax[M_TOT];
__device__ float g_cinv[M_TOT];

// ---------------------------------------------------------------------------
// tf32 helpers
// ---------------------------------------------------------------------------
__device__ __forceinline__ float f2tf(float x) {
    uint32_t r;
    asm("cvt.rna.tf32.f32 %0, %1;" : "=r"(r) : "f"(x));
    return __uint_as_float(r);
}
__device__ __forceinline__ float4 cvt4(float4 v) {
    float4 o; o.x = f2tf(v.x); o.y = f2tf(v.y); o.z = f2tf(v.z); o.w = f2tf(v.w);
    return o;
}
__device__ __forceinline__ void mma_tf32(float d[4], const uint32_t a[4], const uint32_t b[2]) {
    asm volatile(
        "mma.sync.aligned.m16n8k8.row.col.f32.tf32.tf32.f32 "
        "{%0,%1,%2,%3}, {%4,%5,%6,%7}, {%8,%9}, {%0,%1,%2,%3};\n"
        : "+f"(d[0]), "+f"(d[1]), "+f"(d[2]), "+f"(d[3])
        : "r"(a[0]), "r"(a[1]), "r"(a[2]), "r"(a[3]), "r"(b[0]), "r"(b[1]));
}

// ---------------------------------------------------------------------------
// 128x128 tile tf32-MMA core. 256 threads = 8 warps in 2x4; warp tile 64x32.
// A [M,K] row-major (lda), B [K,N] row-major (ldb). Smem k-major [16][136]
// (pad 8 -> conflict-free fragment reads). Register-prefetch pipeline.
// ---------------------------------------------------------------------------
__device__ __forceinline__ void gemm_mma(const float* __restrict__ A, int lda,
                                         const float* __restrict__ B, int ldb,
                                         int rBase, int cBase, int kEnd,
                                         float (*As)[136], float (*Bs)[136],
                                         float acc[4][4][4])
{
    const int tid  = threadIdx.x;
    const int lane = tid & 31;
    const int warp = tid >> 5;
    const int mw = (warp >> 2) * 64;     // 0 or 64
    const int nw = (warp & 3) * 32;      // 0,32,64,96
    const int r  = lane >> 2;            // groupID
    const int c  = lane & 3;             // thread-in-group

    const int arow = tid >> 1;           // 0..127
    const int acol = (tid & 1) * 8;      // 0 or 8
    const int brow = tid >> 4;           // 0..15
    const int bcol = (tid & 15) * 8;     // 0..120

    const float* Ap = A + (size_t)(rBase + arow) * lda + acol;
    const float* Bp = B + (size_t)brow * ldb + cBase + bcol;

    float4 pa0 = *(const float4*)(Ap);
    float4 pa1 = *(const float4*)(Ap + 4);
    float4 pb0 = *(const float4*)(Bp);
    float4 pb1 = *(const float4*)(Bp + 4);

    for (int k0 = 0; k0 < kEnd; k0 += 16) {
        // store current tile to smem (tf32-rounded)
        As[acol + 0][arow] = f2tf(pa0.x);
        As[acol + 1][arow] = f2tf(pa0.y);
        As[acol + 2][arow] = f2tf(pa0.z);
        As[acol + 3][arow] = f2tf(pa0.w);
        As[acol + 4][arow] = f2tf(pa1.x);
        As[acol + 5][arow] = f2tf(pa1.y);
        As[acol + 6][arow] = f2tf(pa1.z);
        As[acol + 7][arow] = f2tf(pa1.w);
        *(float4*)&Bs[brow][bcol]     = cvt4(pb0);
        *(float4*)&Bs[brow][bcol + 4] = cvt4(pb1);
        __syncthreads();

        // prefetch next tile
        if (k0 + 16 < kEnd) {
            pa0 = *(const float4*)(Ap + k0 + 16);
            pa1 = *(const float4*)(Ap + k0 + 20);
            pb0 = *(const float4*)(Bp + (size_t)(k0 + 16) * ldb);
            pb1 = *(const float4*)(Bp + (size_t)(k0 + 16) * ldb + 4);
        }

#pragma unroll
        for (int ks = 0; ks < 2; ++ks) {
            const int kk = ks * 8;
            uint32_t af[4][4], bf[4][2];
#pragma unroll
            for (int mi = 0; mi < 4; ++mi) {
                const int m = mw + mi * 16 + r;
                af[mi][0] = __float_as_uint(As[kk + c][m]);
                af[mi][1] = __float_as_uint(As[kk + c][m + 8]);
                af[mi][2] = __float_as_uint(As[kk + c + 4][m]);
                af[mi][3] = __float_as_uint(As[kk + c + 4][m + 8]);
            }
#pragma unroll
            for (int ni = 0; ni < 4; ++ni) {
                const int n = nw + ni * 8 + r;
                bf[ni][0] = __float_as_uint(Bs[kk + c][n]);
                bf[ni][1] = __float_as_uint(Bs[kk + c + 4][n]);
            }
#pragma unroll
            for (int mi = 0; mi < 4; ++mi)
#pragma unroll
                for (int ni = 0; ni < 4; ++ni)
                    mma_tf32(acc[mi][ni], af[mi], bf[ni]);
        }
        __syncthreads();
    }
}

// Fragment->global coordinates: for acc[mi][ni][reg]:
//   row = rBase + mw + mi*16 + (lane>>2) + (reg>=2 ? 8 : 0)
//   col = cBase + nw + ni*8  + 2*(lane&3) + (reg&1)

// ---------------------------------------------------------------------------
// 1. QKV projection (tensor cores): grid.z selects q/k/v; q pre-scaled.
// ---------------------------------------------------------------------------
__global__ __launch_bounds__(256)
void qkv_kernel(const float* __restrict__ x,
                const float* __restrict__ Wq, const float* __restrict__ bq,
                const float* __restrict__ Wk, const float* __restrict__ bk,
                const float* __restrict__ Wv, const float* __restrict__ bv)
{
    __shared__ float As[16][136];
    __shared__ float Bs[16][136];

    const float* W; const float* bias; float* out; float oscale;
    if (blockIdx.z == 0)      { W = Wq; bias = bq; out = g_q; oscale = SCALE; }
    else if (blockIdx.z == 1) { W = Wk; bias = bk; out = g_k; oscale = 1.0f; }
    else                      { W = Wv; bias = bv; out = g_v; oscale = 1.0f; }

    const int rBase = blockIdx.y * 128;
    const int cBase = blockIdx.x * 128;
    float acc[4][4][4] = {};
    gemm_mma(x, C, W, C, rBase, cBase, C, As, Bs, acc);

    const int lane = threadIdx.x & 31, warp = threadIdx.x >> 5;
    const int mw = (warp >> 2) * 64, nw = (warp & 3) * 32;
    const int r = lane >> 2, cc = lane & 3;
#pragma unroll
    for (int mi = 0; mi < 4; ++mi) {
#pragma unroll
        for (int ni = 0; ni < 4; ++ni) {
            const int row = rBase + mw + mi * 16 + r;
            const int col = cBase + nw + ni * 8 + 2 * cc;
            float b0 = bias[col], b1 = bias[col + 1];
            float2 lo, hi;
            lo.x = (acc[mi][ni][0] + b0) * oscale;
            lo.y = (acc[mi][ni][1] + b1) * oscale;
            hi.x = (acc[mi][ni][2] + b0) * oscale;
            hi.y = (acc[mi][ni][3] + b1) * oscale;
            *(float2*)&out[(size_t)row * C + col]       = lo;
            *(float2*)&out[(size_t)(row + 8) * C + col] = hi;
        }
    }
}

// ---------------------------------------------------------------------------
// 2. Transpose k -> kT per batch: [T,C] -> [C,T]
// ---------------------------------------------------------------------------
__global__ void transpose_kernel()
{
    __shared__ float tile[32][33];
    const int b = blockIdx.z;
    const int t0 = blockIdx.x * 32;
    const int c0 = blockIdx.y * 32;
    const float* src = g_k + (size_t)b * T * C;
    float* dst = g_kT + (size_t)b * C * T;
    const int x = threadIdx.x, y = threadIdx.y;
#pragma unroll
    for (int j = 0; j < 32; j += 8)
        tile[y + j][x] = src[(size_t)(t0 + y + j) * C + c0 + x];
    __syncthreads();
#pragma unroll
    for (int j = 0; j < 32; j += 8)
        dst[(size_t)(c0 + y + j) * T + t0 + x] = tile[x][y + j];
}

// ---------------------------------------------------------------------------
// 3. logits[t,s] = q_scaled[t,:] . k[s,:]; skip strictly-upper tiles.
// ---------------------------------------------------------------------------
__global__ __launch_bounds__(256)
void logits_kernel()
{
    const int bx = blockIdx.x, by = blockIdx.y, b = blockIdx.z;
    if (bx > by) return;   // fully-masked tile
    __shared__ float As[16][136];
    __shared__ float Bs[16][136];
    const int rBase = by * 128;
    const int cBase = bx * 128;
    const float* A  = g_q  + (size_t)b * T * C;
    const float* Bm = g_kT + (size_t)b * C * T;
    float* Cp = g_logits + (size_t)b * T * T;

    float acc[4][4][4] = {};
    gemm_mma(A, C, Bm, T, rBase, cBase, C, As, Bs, acc);

    const int lane = threadIdx.x & 31, warp = threadIdx.x >> 5;
    const int mw = (warp >> 2) * 64, nw = (warp & 3) * 32;
    const int r = lane >> 2, cc = lane & 3;
#pragma unroll
    for (int mi = 0; mi < 4; ++mi) {
#pragma unroll
        for (int ni = 0; ni < 4; ++ni) {
            const int row = rBase + mw + mi * 16 + r;
            const int col = cBase + nw + ni * 8 + 2 * cc;
            *(float2*)&Cp[(size_t)row * T + col]       = make_float2(acc[mi][ni][0], acc[mi][ni][1]);
            *(float2*)&Cp[(size_t)(row + 8) * T + col] = make_float2(acc[mi][ni][2], acc[mi][ni][3]);
        }
    }
}

// ---------------------------------------------------------------------------
// 4. Column stats (softmax over QUERY axis t per key column s).
//    32 columns per block, 8-way row split, online-softmax merge.
// ---------------------------------------------------------------------------
__global__ void colstats_kernel()
{
    __shared__ float sm[8][33];
    __shared__ float sd[8][33];
    const int b = blockIdx.y;
    const int s = blockIdx.x * 32 + threadIdx.x;
    const float* L = g_logits + (size_t)b * T * T;

    float m = -1e30f, d = 0.f;
    for (int t = threadIdx.y; t < T; t += 8) {
        if (t >= s) {
            float l = L[(size_t)t * T + s];
            if (l > m) { d = d * __expf(m - l) + 1.0f; m = l; }
            else       { d += __expf(l - m); }
        }
    }
    sm[threadIdx.y][threadIdx.x] = m;
    sd[threadIdx.y][threadIdx.x] = d;
    __syncthreads();
    if (threadIdx.y == 0) {
#pragma unroll
        for (int j = 1; j < 8; ++j) {
            float m2 = sm[j][threadIdx.x], d2 = sd[j][threadIdx.x];
            float nm = fmaxf(m, m2);
            d = d * __expf(m - nm) + d2 * __expf(m2 - nm);
            m = nm;
        }
        g_cmax[b * T + s] = m;
        g_cinv[b * T + s] = 1.0f / d;
    }
}

// ---------------------------------------------------------------------------
// 5. probs in place: p[t,s] = (s<=t) ? exp(l - cmax[s]) * cinv[s] : 0
// ---------------------------------------------------------------------------
__global__ void probs_kernel()
{
    const int b = blockIdx.z, t = blockIdx.y;
    const int s = (blockIdx.x * blockDim.x + threadIdx.x) << 2;
    const size_t base = (size_t)b * T * T + (size_t)t * T + s;
    float4 l  = *(const float4*)&g_logits[base];
    float4 cm = *(const float4*)&g_cmax[b * T + s];
    float4 ci = *(const float4*)&g_cinv[b * T + s];
    float4 p;
    p.x = (s + 0 <= t) ? __expf(l.x - cm.x) * ci.x : 0.f;
    p.y = (s + 1 <= t) ? __expf(l.y - cm.y) * ci.y : 0.f;
    p.z = (s + 2 <= t) ? __expf(l.z - cm.z) * ci.z : 0.f;
    p.w = (s + 3 <= t) ? __expf(l.w - cm.w) * ci.w : 0.f;
    *(float4*)&g_logits[base] = p;
}

// ---------------------------------------------------------------------------
// 6. read = probs @ v into out[..., 512:1024]; k clamped (causal pruning).
//    Heavy row-tiles launched first (reversed y).
// ---------------------------------------------------------------------------
__global__ __launch_bounds__(256)
void pv_kernel(float* __restrict__ out)
{
    __shared__ float As[16][136];
    __shared__ float Bs[16][136];
    const int b = blockIdx.z;
    const int rTile = (gridDim.y - 1) - blockIdx.y;   // heavy first
    const int rBase = rTile * 128;
    const int cBase = blockIdx.x * 128;
    const float* A  = g_logits + (size_t)b * T * T;   // probs
    const float* Bm = g_v      + (size_t)b * T * C;

    float acc[4][4][4] = {};
    gemm_mma(A, T, Bm, C, rBase, cBase, rBase + 128, As, Bs, acc);

    const int lane = threadIdx.x & 31, warp = threadIdx.x >> 5;
    const int mw = (warp >> 2) * 64, nw = (warp & 3) * 32;
    const int r = lane >> 2, cc = lane & 3;
#pragma unroll
    for (int mi = 0; mi < 4; ++mi) {
#pragma unroll
        for (int ni = 0; ni < 4; ++ni) {
            const int row = rBase + mw + mi * 16 + r;
            const int col = cBase + nw + ni * 8 + 2 * cc;
            float* d0 = out + ((size_t)(b * T + row) * 1024) + 512 + col;
            float* d1 = out + ((size_t)(b * T + row + 8) * 1024) + 512 + col;
            *(float2*)d0 = make_float2(acc[mi][ni][0], acc[mi][ni][1]);
            *(float2*)d1 = make_float2(acc[mi][ni][2], acc[mi][ni][3]);
        }
    }
}

// ---------------------------------------------------------------------------
// 7. out[..., 0:512] = x
// ---------------------------------------------------------------------------
__global__ void copyx_kernel(const float* __restrict__ x, float* __restrict__ out)
{
    const int i = blockIdx.x * blockDim.x + threadIdx.x;   // float4 index
    const int row = i >> 7;
    const int c4  = i & 127;
    ((float4*)out)[(size_t)row * 256 + c4] = ((const float4*)x)[(size_t)row * 128 + c4];
}

// ---------------------------------------------------------------------------
extern "C" void kernel_launch(void* const* d_in, const int* in_sizes, int n_in,
                              void* d_out, int out_size)
{
    const float* x  = (const float*)d_in[0];
    const float* Wq = (const float*)d_in[1];
    const float* bq = (const float*)d_in[2];
    const float* Wk = (const float*)d_in[3];
    const float* bk = (const float*)d_in[4];
    const float* Wv = (const float*)d_in[5];
    const float* bv = (const float*)d_in[6];
    float* out = (float*)d_out;

    qkv_kernel<<<dim3(C / 128, M_TOT / 128, 3), 256>>>(x, Wq, bq, Wk, bk, Wv, bv);
    transpose_kernel<<<dim3(T / 32, C / 32, BATCH), dim3(32, 8)>>>();
    logits_kernel<<<dim3(T / 128, T / 128, BATCH), 256>>>();
    colstats_kernel<<<dim3(T / 32, BATCH), dim3(32, 8)>>>();
    probs_kernel<<<dim3(T / 1024, T, BATCH), 256>>>();
    pv_kernel<<<dim3(C / 128, T / 128, BATCH), 256>>>(out);
    copyx_kernel<<<(M_TOT * 128) / 256, 256>>>(x, out);
}

// round 3
// speedup vs baseline: 2.7581x; 1.1630x over previous
#include <cuda_runtime.h>
#include <cstdint>

// Problem constants
constexpr int BATCH = 8;
constexpr int T = 2048;
constexpr int C = 512;                 // IN_CH = KEY = VAL = 512
constexpr int M_TOT = BATCH * T;       // 16384
constexpr int CHUNKS = 8;              // colstats row-split
constexpr float SCALE = 0.044194173824159216f; // 1/sqrt(512)

// Scratch (device globals: allocation-free rule)
__device__ float g_q[M_TOT * C];       // pre-scaled by SCALE
__device__ float g_k[M_TOT * C];
__device__ float g_v[M_TOT * C];
__device__ float g_logits[(size_t)BATCH * T * T];   // raw logits (lower triangle valid)
__device__ float g_pm[CHUNKS * M_TOT];  // partial col max
__device__ float g_pd[CHUNKS * M_TOT];  // partial col denom
__device__ float g_cmax[M_TOT];
__device__ float g_cinv[M_TOT];

// ---------------------------------------------------------------------------
// tf32 helpers
// ---------------------------------------------------------------------------
__device__ __forceinline__ float f2tf(float x) {
    uint32_t r;
    asm("cvt.rna.tf32.f32 %0, %1;" : "=r"(r) : "f"(x));
    return __uint_as_float(r);
}
__device__ __forceinline__ float4 cvt4(float4 v) {
    float4 o; o.x = f2tf(v.x); o.y = f2tf(v.y); o.z = f2tf(v.z); o.w = f2tf(v.w);
    return o;
}
__device__ __forceinline__ void mma_tf32(float d[4], const uint32_t a[4], const uint32_t b[2]) {
    asm volatile(
        "mma.sync.aligned.m16n8k8.row.col.f32.tf32.tf32.f32 "
        "{%0,%1,%2,%3}, {%4,%5,%6,%7}, {%8,%9}, {%0,%1,%2,%3};\n"
        : "+f"(d[0]), "+f"(d[1]), "+f"(d[2]), "+f"(d[3])
        : "r"(a[0]), "r"(a[1]), "r"(a[2]), "r"(a[3]), "r"(b[0]), "r"(b[1]));
}

// ---------------------------------------------------------------------------
// 128x128 tile tf32-MMA core. 256 threads = 8 warps in 2x4; warp tile 64x32.
// A [M,K] row-major. B: if BT, [N,K] row-major (transposed in smem store);
// else [K,N] row-major. Smem k-major [16][136] (pad 8 -> conflict-free).
// If EXPA: A element (t,s) is transformed exp(a - cmx[s]) * cin[s], masked
// to 0 for s > t (fused softmax-probs for the PV GEMM).
// ---------------------------------------------------------------------------
template<bool BT, bool EXPA>
__device__ __forceinline__ void gemm_mma(const float* __restrict__ A, int lda,
                                         const float* __restrict__ B, int ldb,
                                         int rBase, int cBase, int kEnd,
                                         const float* __restrict__ cmx,
                                         const float* __restrict__ cin,
                                         float (*As)[136], float (*Bs)[136],
                                         float acc[4][4][4])
{
    const int tid  = threadIdx.x;
    const int lane = tid & 31;
    const int warp = tid >> 5;
    const int mw = (warp >> 2) * 64;     // 0 or 64
    const int nw = (warp & 3) * 32;      // 0,32,64,96
    const int r  = lane >> 2;
    const int c  = lane & 3;

    // transposing loader indices (A always, B when BT)
    const int arow = tid >> 1;           // 0..127
    const int acol = (tid & 1) * 8;      // 0 or 8
    const int trow = rBase + arow;       // query row for EXPA mask
    // dense loader indices (B when !BT)
    const int brow = tid >> 4;           // 0..15
    const int bcol = (tid & 15) * 8;     // 0..120

    const float* Ap = A + (size_t)trow * lda + acol;
    const float* Bp = BT ? (B + (size_t)(cBase + arow) * ldb + acol)
                         : (B + (size_t)brow * ldb + cBase + bcol);

    float4 pa0 = *(const float4*)(Ap);
    float4 pa1 = *(const float4*)(Ap + 4);
    float4 pb0 = *(const float4*)(Bp);
    float4 pb1 = *(const float4*)(Bp + 4);
    float4 pm0, pm1, pi0, pi1;
    if (EXPA) {
        pm0 = *(const float4*)&cmx[acol]; pm1 = *(const float4*)&cmx[acol + 4];
        pi0 = *(const float4*)&cin[acol]; pi1 = *(const float4*)&cin[acol + 4];
    }

    for (int k0 = 0; k0 < kEnd; k0 += 16) {
        // ---- store current tiles (tf32-rounded; A optionally exp-masked) ----
        if (EXPA) {
            float av[8] = {pa0.x, pa0.y, pa0.z, pa0.w, pa1.x, pa1.y, pa1.z, pa1.w};
            float mv[8] = {pm0.x, pm0.y, pm0.z, pm0.w, pm1.x, pm1.y, pm1.z, pm1.w};
            float iv[8] = {pi0.x, pi0.y, pi0.z, pi0.w, pi1.x, pi1.y, pi1.z, pi1.w};
#pragma unroll
            for (int j = 0; j < 8; ++j) {
                const int s = k0 + acol + j;
                float p = (s <= trow) ? __expf(av[j] - mv[j]) * iv[j] : 0.0f;
                As[acol + j][arow] = f2tf(p);
            }
        } else {
            As[acol + 0][arow] = f2tf(pa0.x);
            As[acol + 1][arow] = f2tf(pa0.y);
            As[acol + 2][arow] = f2tf(pa0.z);
            As[acol + 3][arow] = f2tf(pa0.w);
            As[acol + 4][arow] = f2tf(pa1.x);
            As[acol + 5][arow] = f2tf(pa1.y);
            As[acol + 6][arow] = f2tf(pa1.z);
            As[acol + 7][arow] = f2tf(pa1.w);
        }
        if (BT) {
            Bs[acol + 0][arow] = f2tf(pb0.x);
            Bs[acol + 1][arow] = f2tf(pb0.y);
            Bs[acol + 2][arow] = f2tf(pb0.z);
            Bs[acol + 3][arow] = f2tf(pb0.w);
            Bs[acol + 4][arow] = f2tf(pb1.x);
            Bs[acol + 5][arow] = f2tf(pb1.y);
            Bs[acol + 6][arow] = f2tf(pb1.z);
            Bs[acol + 7][arow] = f2tf(pb1.w);
        } else {
            *(float4*)&Bs[brow][bcol]     = cvt4(pb0);
            *(float4*)&Bs[brow][bcol + 4] = cvt4(pb1);
        }
        __syncthreads();

        // ---- prefetch next tiles ----
        if (k0 + 16 < kEnd) {
            pa0 = *(const float4*)(Ap + k0 + 16);
            pa1 = *(const float4*)(Ap + k0 + 20);
            if (BT) {
                pb0 = *(const float4*)(Bp + k0 + 16);
                pb1 = *(const float4*)(Bp + k0 + 20);
            } else {
                pb0 = *(const float4*)(Bp + (size_t)(k0 + 16) * ldb);
                pb1 = *(const float4*)(Bp + (size_t)(k0 + 16) * ldb + 4);
            }
            if (EXPA) {
                pm0 = *(const float4*)&cmx[k0 + 16 + acol];
                pm1 = *(const float4*)&cmx[k0 + 20 + acol];
                pi0 = *(const float4*)&cin[k0 + 16 + acol];
                pi1 = *(const float4*)&cin[k0 + 20 + acol];
            }
        }

        // ---- MMA over the 16-deep tile ----
#pragma unroll
        for (int ks = 0; ks < 2; ++ks) {
            const int kk = ks * 8;
            uint32_t af[4][4], bf[4][2];
#pragma unroll
            for (int mi = 0; mi < 4; ++mi) {
                const int m = mw + mi * 16 + r;
                af[mi][0] = __float_as_uint(As[kk + c][m]);
                af[mi][1] = __float_as_uint(As[kk + c][m + 8]);
                af[mi][2] = __float_as_uint(As[kk + c + 4][m]);
                af[mi][3] = __float_as_uint(As[kk + c + 4][m + 8]);
            }
#pragma unroll
            for (int ni = 0; ni < 4; ++ni) {
                const int n = nw + ni * 8 + r;
                bf[ni][0] = __float_as_uint(Bs[kk + c][n]);
                bf[ni][1] = __float_as_uint(Bs[kk + c + 4][n]);
            }
#pragma unroll
            for (int mi = 0; mi < 4; ++mi)
#pragma unroll
                for (int ni = 0; ni < 4; ++ni)
                    mma_tf32(acc[mi][ni], af[mi], bf[ni]);
        }
        __syncthreads();
    }
}

// Fragment->global: acc[mi][ni][reg]:
//   row = rBase + mw + mi*16 + (lane>>2) + (reg>=2 ? 8 : 0)
//   col = cBase + nw + ni*8  + 2*(lane&3) + (reg&1)

// ---------------------------------------------------------------------------
// 1. QKV projection: grid.z selects q/k/v; q pre-scaled by 1/sqrt(K).
// ---------------------------------------------------------------------------
__global__ __launch_bounds__(256)
void qkv_kernel(const float* __restrict__ x,
                const float* __restrict__ Wq, const float* __restrict__ bq,
                const float* __restrict__ Wk, const float* __restrict__ bk,
                const float* __restrict__ Wv, const float* __restrict__ bv)
{
    __shared__ float As[16][136];
    __shared__ float Bs[16][136];

    const float* W; const float* bias; float* out; float oscale;
    if (blockIdx.z == 0)      { W = Wq; bias = bq; out = g_q; oscale = SCALE; }
    else if (blockIdx.z == 1) { W = Wk; bias = bk; out = g_k; oscale = 1.0f; }
    else                      { W = Wv; bias = bv; out = g_v; oscale = 1.0f; }

    const int rBase = blockIdx.y * 128;
    const int cBase = blockIdx.x * 128;
    float acc[4][4][4] = {};
    gemm_mma<false, false>(x, C, W, C, rBase, cBase, C, nullptr, nullptr, As, Bs, acc);

    const int lane = threadIdx.x & 31, warp = threadIdx.x >> 5;
    const int mw = (warp >> 2) * 64, nw = (warp & 3) * 32;
    const int r = lane >> 2, cc = lane & 3;
#pragma unroll
    for (int mi = 0; mi < 4; ++mi) {
#pragma unroll
        for (int ni = 0; ni < 4; ++ni) {
            const int row = rBase + mw + mi * 16 + r;
            const int col = cBase + nw + ni * 8 + 2 * cc;
            float b0 = bias[col], b1 = bias[col + 1];
            float2 lo, hi;
            lo.x = (acc[mi][ni][0] + b0) * oscale;
            lo.y = (acc[mi][ni][1] + b1) * oscale;
            hi.x = (acc[mi][ni][2] + b0) * oscale;
            hi.y = (acc[mi][ni][3] + b1) * oscale;
            *(float2*)&out[(size_t)row * C + col]       = lo;
            *(float2*)&out[(size_t)(row + 8) * C + col] = hi;
        }
    }
}

// ---------------------------------------------------------------------------
// 2. logits[t,s] = q_scaled[t,:] . k[s,:]; B transposed in-loader.
//    Strictly-upper tiles skipped (never read downstream).
// ---------------------------------------------------------------------------
__global__ __launch_bounds__(256)
void logits_kernel()
{
    const int bx = blockIdx.x, by = blockIdx.y, b = blockIdx.z;
    if (bx > by) return;
    __shared__ float As[16][136];
    __shared__ float Bs[16][136];
    const int rBase = by * 128;
    const int cBase = bx * 128;
    const float* A  = g_q + (size_t)b * T * C;
    const float* Bm = g_k + (size_t)b * T * C;
    float* Cp = g_logits + (size_t)b * T * T;

    float acc[4][4][4] = {};
    gemm_mma<true, false>(A, C, Bm, C, rBase, cBase, C, nullptr, nullptr, As, Bs, acc);

    const int lane = threadIdx.x & 31, warp = threadIdx.x >> 5;
    const int mw = (warp >> 2) * 64, nw = (warp & 3) * 32;
    const int r = lane >> 2, cc = lane & 3;
#pragma unroll
    for (int mi = 0; mi < 4; ++mi) {
#pragma unroll
        for (int ni = 0; ni < 4; ++ni) {
            const int row = rBase + mw + mi * 16 + r;
            const int col = cBase + nw + ni * 8 + 2 * cc;
            *(float2*)&Cp[(size_t)row * T + col]       = make_float2(acc[mi][ni][0], acc[mi][ni][1]);
            *(float2*)&Cp[(size_t)(row + 8) * T + col] = make_float2(acc[mi][ni][2], acc[mi][ni][3]);
        }
    }
}

// ---------------------------------------------------------------------------
// 3a. Partial column stats: chunk z covers rows [z*256, z*256+256).
//     Online softmax over t >= s within the chunk.
// ---------------------------------------------------------------------------
__global__ void colstats_kernel()
{
    __shared__ float sm[8][33];
    __shared__ float sd[8][33];
    const int b  = blockIdx.y;
    const int ch = blockIdx.z;
    const int s  = blockIdx.x * 32 + threadIdx.x;
    const int t0 = ch * 256;

    float m = -1e30f, d = 0.f;
    if (t0 + 255 >= s) {
        const float* L = g_logits + (size_t)b * T * T;
        for (int t = t0 + threadIdx.y; t < t0 + 256; t += 8) {
            if (t >= s) {
                float l = L[(size_t)t * T + s];
                if (l > m) { d = d * __expf(m - l) + 1.0f; m = l; }
                else       { d += __expf(l - m); }
            }
        }
    }
    sm[threadIdx.y][threadIdx.x] = m;
    sd[threadIdx.y][threadIdx.x] = d;
    __syncthreads();
    if (threadIdx.y == 0) {
#pragma unroll
        for (int j = 1; j < 8; ++j) {
            float m2 = sm[j][threadIdx.x], d2 = sd[j][threadIdx.x];
            float nm = fmaxf(m, m2);
            d = d * __expf(m - nm) + d2 * __expf(m2 - nm);
            m = nm;
        }
        g_pm[ch * M_TOT + b * T + s] = m;
        g_pd[ch * M_TOT + b * T + s] = d;
    }
}

// 3b. Merge partials -> cmax, 1/sum
__global__ void colmerge_kernel()
{
    const int i = blockIdx.x * blockDim.x + threadIdx.x;
    float m = -1e30f, d = 0.f;
#pragma unroll
    for (int ch = 0; ch < CHUNKS; ++ch) {
        float m2 = g_pm[ch * M_TOT + i], d2 = g_pd[ch * M_TOT + i];
        float nm = fmaxf(m, m2);
        d = d * __expf(m - nm) + d2 * __expf(m2 - nm);
        m = nm;
    }
    g_cmax[i] = m;
    g_cinv[i] = 1.0f / d;
}

// ---------------------------------------------------------------------------
// 4. read = softmax(logits) @ v into out[..., 512:1024].
//    exp/mask/normalize fused into the A-tile loader; k clamped (causal).
// ---------------------------------------------------------------------------
__global__ __launch_bounds__(256)
void pv_kernel(float* __restrict__ out)
{
    __shared__ float As[16][136];
    __shared__ float Bs[16][136];
    const int b = blockIdx.z;
    const int rTile = (gridDim.y - 1) - blockIdx.y;   // heavy tiles first
    const int rBase = rTile * 128;
    const int cBase = blockIdx.x * 128;
    const float* A  = g_logits + (size_t)b * T * T;
    const float* Bm = g_v      + (size_t)b * T * C;
    const float* cm = g_cmax + b * T;
    const float* ci = g_cinv + b * T;

    float acc[4][4][4] = {};
    gemm_mma<false, true>(A, T, Bm, C, rBase, cBase, rBase + 128, cm, ci, As, Bs, acc);

    const int lane = threadIdx.x & 31, warp = threadIdx.x >> 5;
    const int mw = (warp >> 2) * 64, nw = (warp & 3) * 32;
    const int r = lane >> 2, cc = lane & 3;
#pragma unroll
    for (int mi = 0; mi < 4; ++mi) {
#pragma unroll
        for (int ni = 0; ni < 4; ++ni) {
            const int row = rBase + mw + mi * 16 + r;
            const int col = cBase + nw + ni * 8 + 2 * cc;
            float* d0 = out + ((size_t)(b * T + row) * 1024) + 512 + col;
            float* d1 = out + ((size_t)(b * T + row + 8) * 1024) + 512 + col;
            *(float2*)d0 = make_float2(acc[mi][ni][0], acc[mi][ni][1]);
            *(float2*)d1 = make_float2(acc[mi][ni][2], acc[mi][ni][3]);
        }
    }
}

// ---------------------------------------------------------------------------
// 5. out[..., 0:512] = x
// ---------------------------------------------------------------------------
__global__ void copyx_kernel(const float* __restrict__ x, float* __restrict__ out)
{
    const int i = blockIdx.x * blockDim.x + threadIdx.x;   // float4 index
    const int row = i >> 7;
    const int c4  = i & 127;
    ((float4*)out)[(size_t)row * 256 + c4] = ((const float4*)x)[(size_t)row * 128 + c4];
}

// ---------------------------------------------------------------------------
extern "C" void kernel_launch(void* const* d_in, const int* in_sizes, int n_in,
                              void* d_out, int out_size)
{
    const float* x  = (const float*)d_in[0];
    const float* Wq = (const float*)d_in[1];
    const float* bq = (const float*)d_in[2];
    const float* Wk = (const float*)d_in[3];
    const float* bk = (const float*)d_in[4];
    const float* Wv = (const float*)d_in[5];
    const float* bv = (const float*)d_in[6];
    float* out = (float*)d_out;

    qkv_kernel<<<dim3(C / 128, M_TOT / 128, 3), 256>>>(x, Wq, bq, Wk, bk, Wv, bv);
    logits_kernel<<<dim3(T / 128, T / 128, BATCH), 256>>>();
    colstats_kernel<<<dim3(T / 32, BATCH, CHUNKS), dim3(32, 8)>>>();
    colmerge_kernel<<<M_TOT / 256, 256>>>();
    pv_kernel<<<dim3(C / 128, T / 128, BATCH), 256>>>(out);
    copyx_kernel<<<(M_TOT * 128) / 256, 256>>>(x, out);
}

// round 5
// speedup vs baseline: 2.9802x; 1.0805x over previous
#include <cuda_runtime.h>
#include <cstdint>

// Problem constants
constexpr int BATCH = 8;
constexpr int T = 2048;
constexpr int C = 512;                 // IN_CH = KEY = VAL = 512
constexpr int M_TOT = BATCH * T;       // 16384
constexpr int CHUNKS = 8;              // colstats row-split
constexpr float SCALE = 0.044194173824159216f; // 1/sqrt(512)

constexpr int AK = 20;                 // padded k-stride for [m][k] smem tiles

// Scratch (device globals: allocation-free rule)
__device__ float g_q[M_TOT * C];       // pre-scaled by SCALE
__device__ float g_k[M_TOT * C];
__device__ float g_v[M_TOT * C];
__device__ float g_logits[(size_t)BATCH * T * T];   // raw logits (lower triangle valid)
__device__ float g_pm[CHUNKS * M_TOT];
__device__ float g_pd[CHUNKS * M_TOT];
__device__ float g_cmax[M_TOT];
__device__ float g_cinv[M_TOT];

// ---------------------------------------------------------------------------
// helpers
// ---------------------------------------------------------------------------
__device__ __forceinline__ void mma_tf32(float d[4], const uint32_t a[4], const uint32_t b[2]) {
    asm volatile(
        "mma.sync.aligned.m16n8k8.row.col.f32.tf32.tf32.f32 "
        "{%0,%1,%2,%3}, {%4,%5,%6,%7}, {%8,%9}, {%0,%1,%2,%3};\n"
        : "+f"(d[0]), "+f"(d[1]), "+f"(d[2]), "+f"(d[3])
        : "r"(a[0]), "r"(a[1]), "r"(a[2]), "r"(a[3]), "r"(b[0]), "r"(b[1]));
}
__device__ __forceinline__ uint32_t smem_u32(const void* p) {
    return (uint32_t)__cvta_generic_to_shared(p);
}
#define CP16(dst, src) asm volatile("cp.async.ca.shared.global [%0], [%1], 16;" :: "r"(dst), "l"(src))
#define CP_COMMIT()    asm volatile("cp.async.commit_group;")
#define CP_WAIT(n)     asm volatile("cp.async.wait_group %0;" :: "n"(n))

// ---------------------------------------------------------------------------
// MMA consume: 128x128x16 tile. As is [128][AK] row-major (m,k).
// If BNK: Bs is [128][AK] (n,k) [transposed-B]; else [16][136] (k,n).
// Raw f32 bits fed to tf32 MMA (HW truncates mantissa).
// ---------------------------------------------------------------------------
template<bool BNK>
__device__ __forceinline__ void mma_consume(const float* __restrict__ As,
                                            const float* __restrict__ Bs,
                                            int mw, int nw, int r, int c,
                                            float acc[4][4][4])
{
#pragma unroll
    for (int ks = 0; ks < 2; ++ks) {
        const int kk = ks * 8;
        uint32_t af[4][4], bf[4][2];
#pragma unroll
        for (int mi = 0; mi < 4; ++mi) {
            const int m = mw + mi * 16 + r;
            af[mi][0] = __float_as_uint(As[m * AK + kk + c]);
            af[mi][1] = __float_as_uint(As[(m + 8) * AK + kk + c]);
            af[mi][2] = __float_as_uint(As[m * AK + kk + c + 4]);
            af[mi][3] = __float_as_uint(As[(m + 8) * AK + kk + c + 4]);
        }
#pragma unroll
        for (int ni = 0; ni < 4; ++ni) {
            const int n = nw + ni * 8 + r;
            if (BNK) {
                bf[ni][0] = __float_as_uint(Bs[n * AK + kk + c]);
                bf[ni][1] = __float_as_uint(Bs[n * AK + kk + c + 4]);
            } else {
                bf[ni][0] = __float_as_uint(Bs[(kk + c) * 136 + n]);
                bf[ni][1] = __float_as_uint(Bs[(kk + c + 4) * 136 + n]);
            }
        }
#pragma unroll
        for (int mi = 0; mi < 4; ++mi)
#pragma unroll
            for (int ni = 0; ni < 4; ++ni)
                mma_tf32(acc[mi][ni], af[mi], bf[ni]);
    }
}

// Fragment->global: acc[mi][ni][reg]:
//   row = rBase + mw + mi*16 + (lane>>2) + (reg>=2 ? 8 : 0)
//   col = cBase + nw + ni*8  + 2*(lane&3) + (reg&1)

// ---------------------------------------------------------------------------
// 1. QKV projection: cp.async double-buffered; q pre-scaled by 1/sqrt(K).
// ---------------------------------------------------------------------------
__global__ __launch_bounds__(256)
void qkv_kernel(const float* __restrict__ x,
                const float* __restrict__ Wq, const float* __restrict__ bq,
                const float* __restrict__ Wk, const float* __restrict__ bk,
                const float* __restrict__ Wv, const float* __restrict__ bv)
{
    __shared__ float As[2][128 * AK];
    __shared__ float Bs[2][16 * 136];

    const float* W; const float* bias; float* out; float oscale;
    if (blockIdx.z == 0)      { W = Wq; bias = bq; out = g_q; oscale = SCALE; }
    else if (blockIdx.z == 1) { W = Wk; bias = bk; out = g_k; oscale = 1.0f; }
    else                      { W = Wv; bias = bv; out = g_v; oscale = 1.0f; }

    const int rBase = blockIdx.y * 128;
    const int cBase = blockIdx.x * 128;
    const int tid = threadIdx.x, lane = tid & 31, warp = tid >> 5;
    const int mw = (warp >> 2) * 64, nw = (warp & 3) * 32;
    const int r = lane >> 2, cc = lane & 3;

    const int arow = tid >> 1, ahalf = (tid & 1) * 8;
    const int brow = tid >> 4, bseg = (tid & 15) * 8;
    const float* Asrc = x + (size_t)(rBase + arow) * C + ahalf;
    const float* Bsrc = W + (size_t)brow * C + cBase + bseg;
    uint32_t adst[2], bdst[2];
#pragma unroll
    for (int s = 0; s < 2; ++s) {
        adst[s] = smem_u32(&As[s][arow * AK + ahalf]);
        bdst[s] = smem_u32(&Bs[s][brow * 136 + bseg]);
    }

    auto issue = [&](int st, int k0) {
        CP16(adst[st],      Asrc + k0);
        CP16(adst[st] + 16, Asrc + k0 + 4);
        CP16(bdst[st],      Bsrc + (size_t)k0 * C);
        CP16(bdst[st] + 16, Bsrc + (size_t)k0 * C + 4);
        CP_COMMIT();
    };

    float acc[4][4][4] = {};
    constexpr int NIT = C / 16;
    issue(0, 0);
    for (int it = 0; it < NIT; ++it) {
        if (it + 1 < NIT) { issue((it + 1) & 1, (it + 1) * 16); CP_WAIT(1); }
        else              { CP_WAIT(0); }
        __syncthreads();
        mma_consume<false>(As[it & 1], Bs[it & 1], mw, nw, r, cc, acc);
        __syncthreads();
    }

#pragma unroll
    for (int mi = 0; mi < 4; ++mi) {
#pragma unroll
        for (int ni = 0; ni < 4; ++ni) {
            const int row = rBase + mw + mi * 16 + r;
            const int col = cBase + nw + ni * 8 + 2 * cc;
            float b0 = bias[col], b1 = bias[col + 1];
            float2 lo, hi;
            lo.x = (acc[mi][ni][0] + b0) * oscale;
            lo.y = (acc[mi][ni][1] + b1) * oscale;
            hi.x = (acc[mi][ni][2] + b0) * oscale;
            hi.y = (acc[mi][ni][3] + b1) * oscale;
            *(float2*)&out[(size_t)row * C + col]       = lo;
            *(float2*)&out[(size_t)(row + 8) * C + col] = hi;
        }
    }
}

// ---------------------------------------------------------------------------
// 2. logits = q . k^T; both operands cp.async into [row][k] tiles.
// ---------------------------------------------------------------------------
__global__ __launch_bounds__(256)
void logits_kernel()
{
    const int bx = blockIdx.x, by = blockIdx.y, b = blockIdx.z;
    if (bx > by) return;
    __shared__ float As[2][128 * AK];
    __shared__ float Bn[2][128 * AK];

    const int rBase = by * 128;
    const int cBase = bx * 128;
    const float* A  = g_q + (size_t)b * T * C;
    const float* Bm = g_k + (size_t)b * T * C;
    float* Cp = g_logits + (size_t)b * T * T;

    const int tid = threadIdx.x, lane = tid & 31, warp = tid >> 5;
    const int mw = (warp >> 2) * 64, nw = (warp & 3) * 32;
    const int r = lane >> 2, cc = lane & 3;

    const int arow = tid >> 1, ahalf = (tid & 1) * 8;
    const float* Asrc = A  + (size_t)(rBase + arow) * C + ahalf;
    const float* Bsrc = Bm + (size_t)(cBase + arow) * C + ahalf;
    uint32_t adst[2], bdst[2];
#pragma unroll
    for (int s = 0; s < 2; ++s) {
        adst[s] = smem_u32(&As[s][arow * AK + ahalf]);
        bdst[s] = smem_u32(&Bn[s][arow * AK + ahalf]);
    }

    auto issue = [&](int st, int k0) {
        CP16(adst[st],      Asrc + k0);
        CP16(adst[st] + 16, Asrc + k0 + 4);
        CP16(bdst[st],      Bsrc + k0);
        CP16(bdst[st] + 16, Bsrc + k0 + 4);
        CP_COMMIT();
    };

    float acc[4][4][4] = {};
    constexpr int NIT = C / 16;
    issue(0, 0);
    for (int it = 0; it < NIT; ++it) {
        if (it + 1 < NIT) { issue((it + 1) & 1, (it + 1) * 16); CP_WAIT(1); }
        else              { CP_WAIT(0); }
        __syncthreads();
        mma_consume<true>(As[it & 1], Bn[it & 1], mw, nw, r, cc, acc);
        __syncthreads();
    }

#pragma unroll
    for (int mi = 0; mi < 4; ++mi) {
#pragma unroll
        for (int ni = 0; ni < 4; ++ni) {
            const int row = rBase + mw + mi * 16 + r;
            const int col = cBase + nw + ni * 8 + 2 * cc;
            *(float2*)&Cp[(size_t)row * T + col]       = make_float2(acc[mi][ni][0], acc[mi][ni][1]);
            *(float2*)&Cp[(size_t)(row + 8) * T + col] = make_float2(acc[mi][ni][2], acc[mi][ni][3]);
        }
    }
}

// ---------------------------------------------------------------------------
// 3a. Partial column stats (softmax over query axis t, per key column s).
// ---------------------------------------------------------------------------
__global__ void colstats_kernel()
{
    __shared__ float sm[8][33];
    __shared__ float sd[8][33];
    const int b  = blockIdx.y;
    const int ch = blockIdx.z;
    const int s  = blockIdx.x * 32 + threadIdx.x;
    const int t0 = ch * 256;

    float m = -1e30f, d = 0.f;
    if (t0 + 255 >= s) {
        const float* L = g_logits + (size_t)b * T * T;
        for (int t = t0 + threadIdx.y; t < t0 + 256; t += 8) {
            if (t >= s) {
                float l = L[(size_t)t * T + s];
                if (l > m) { d = d * __expf(m - l) + 1.0f; m = l; }
                else       { d += __expf(l - m); }
            }
        }
    }
    sm[threadIdx.y][threadIdx.x] = m;
    sd[threadIdx.y][threadIdx.x] = d;
    __syncthreads();
    if (threadIdx.y == 0) {
#pragma unroll
        for (int j = 1; j < 8; ++j) {
            float m2 = sm[j][threadIdx.x], d2 = sd[j][threadIdx.x];
            float nm = fmaxf(m, m2);
            d = d * __expf(m - nm) + d2 * __expf(m2 - nm);
            m = nm;
        }
        g_pm[ch * M_TOT + b * T + s] = m;
        g_pd[ch * M_TOT + b * T + s] = d;
    }
}

// 3b. Merge partials -> cmax, 1/sum
__global__ void colmerge_kernel()
{
    const int i = blockIdx.x * blockDim.x + threadIdx.x;
    float m = -1e30f, d = 0.f;
#pragma unroll
    for (int ch = 0; ch < CHUNKS; ++ch) {
        float m2 = g_pm[ch * M_TOT + i], d2 = g_pd[ch * M_TOT + i];
        float nm = fmaxf(m, m2);
        d = d * __expf(m - nm) + d2 * __expf(m2 - nm);
        m = nm;
    }
    g_cmax[i] = m;
    g_cinv[i] = 1.0f / d;
}

// ---------------------------------------------------------------------------
// 4. read = softmax(logits) @ v. A path manual (exp/mask fused into the
//    smem store); B path cp.async. Double buffered. k clamped (causal).
// ---------------------------------------------------------------------------
__global__ __launch_bounds__(256)
void pv_kernel(float* __restrict__ out)
{
    __shared__ float As[2][128 * AK];
    __shared__ float Bs[2][16 * 136];

    const int b = blockIdx.z;
    const int rTile = (gridDim.y - 1) - blockIdx.y;   // heavy tiles first
    const int rBase = rTile * 128;
    const int cBase = blockIdx.x * 128;
    const float* A  = g_logits + (size_t)b * T * T;
    const float* Bm = g_v      + (size_t)b * T * C;
    const float* cm = g_cmax + b * T;
    const float* ci = g_cinv + b * T;

    const int tid = threadIdx.x, lane = tid & 31, warp = tid >> 5;
    const int mw = (warp >> 2) * 64, nw = (warp & 3) * 32;
    const int r = lane >> 2, cc = lane & 3;

    const int arow = tid >> 1, ahalf = (tid & 1) * 8;
    const int trow = rBase + arow;
    const int brow = tid >> 4, bseg = (tid & 15) * 8;
    const float* Asrc = A  + (size_t)trow * T + ahalf;
    const float* Bsrc = Bm + (size_t)brow * C + cBase + bseg;
    float* asw[2];
    uint32_t bdst[2];
#pragma unroll
    for (int s = 0; s < 2; ++s) {
        asw[s]  = &As[s][arow * AK + ahalf];
        bdst[s] = smem_u32(&Bs[s][brow * 136 + bseg]);
    }

    const int NIT = (rBase + 128) / 16;

    // prologue: A regs for k0=0, B stage 0
    float4 pa0 = *(const float4*)(Asrc);
    float4 pa1 = *(const float4*)(Asrc + 4);
    float4 pm0 = *(const float4*)&cm[ahalf];
    float4 pm1 = *(const float4*)&cm[ahalf + 4];
    float4 pi0 = *(const float4*)&ci[ahalf];
    float4 pi1 = *(const float4*)&ci[ahalf + 4];
    CP16(bdst[0],      Bsrc);
    CP16(bdst[0] + 16, Bsrc + 4);
    CP_COMMIT();

    float acc[4][4][4] = {};
    for (int it = 0; it < NIT; ++it) {
        const int k0 = it * 16;
        // transform + store A tile (probs) into stage it&1
        {
            float av[8] = {pa0.x, pa0.y, pa0.z, pa0.w, pa1.x, pa1.y, pa1.z, pa1.w};
            float mv[8] = {pm0.x, pm0.y, pm0.z, pm0.w, pm1.x, pm1.y, pm1.z, pm1.w};
            float iv[8] = {pi0.x, pi0.y, pi0.z, pi0.w, pi1.x, pi1.y, pi1.z, pi1.w};
            float p[8];
#pragma unroll
            for (int j = 0; j < 8; ++j) {
                const int s = k0 + ahalf + j;
                p[j] = (s <= trow) ? __expf(av[j] - mv[j]) * iv[j] : 0.0f;
            }
            *(float4*)(asw[it & 1])     = make_float4(p[0], p[1], p[2], p[3]);
            *(float4*)(asw[it & 1] + 4) = make_float4(p[4], p[5], p[6], p[7]);
        }
        if (it + 1 < NIT) {
            const int kn = k0 + 16;
            pa0 = *(const float4*)(Asrc + kn);
            pa1 = *(const float4*)(Asrc + kn + 4);
            pm0 = *(const float4*)&cm[kn + ahalf];
            pm1 = *(const float4*)&cm[kn + ahalf + 4];
            pi0 = *(const float4*)&ci[kn + ahalf];
            pi1 = *(const float4*)&ci[kn + ahalf + 4];
            const int st = (it + 1) & 1;
            CP16(bdst[st],      Bsrc + (size_t)kn * C);
            CP16(bdst[st] + 16, Bsrc + (size_t)kn * C + 4);
            CP_COMMIT();
            CP_WAIT(1);
        } else {
            CP_WAIT(0);
        }
        __syncthreads();
        mma_consume<false>(As[it & 1], Bs[it & 1], mw, nw, r, cc, acc);
        __syncthreads();
    }

#pragma unroll
    for (int mi = 0; mi < 4; ++mi) {
#pragma unroll
        for (int ni = 0; ni < 4; ++ni) {
            const int row = rBase + mw + mi * 16 + r;
            const int col = cBase + nw + ni * 8 + 2 * cc;
            float* d0 = out + ((size_t)(b * T + row) * 1024) + 512 + col;
            float* d1 = out + ((size_t)(b * T + row + 8) * 1024) + 512 + col;
            *(float2*)d0 = make_float2(acc[mi][ni][0], acc[mi][ni][1]);
            *(float2*)d1 = make_float2(acc[mi][ni][2], acc[mi][ni][3]);
        }
    }
}

// ---------------------------------------------------------------------------
// 5. out[..., 0:512] = x
// ---------------------------------------------------------------------------
__global__ void copyx_kernel(const float* __restrict__ x, float* __restrict__ out)
{
    const int i = blockIdx.x * blockDim.x + threadIdx.x;   // float4 index
    const int row = i >> 7;
    const int c4  = i & 127;
    ((float4*)out)[(size_t)row * 256 + c4] = ((const float4*)x)[(size_t)row * 128 + c4];
}

// ---------------------------------------------------------------------------
extern "C" void kernel_launch(void* const* d_in, const int* in_sizes, int n_in,
                              void* d_out, int out_size)
{
    const float* x  = (const float*)d_in[0];
    const float* Wq = (const float*)d_in[1];
    const float* bq = (const float*)d_in[2];
    const float* Wk = (const float*)d_in[3];
    const float* bk = (const float*)d_in[4];
    const float* Wv = (const float*)d_in[5];
    const float* bv = (const float*)d_in[6];
    float* out = (float*)d_out;

    qkv_kernel<<<dim3(C / 128, M_TOT / 128, 3), 256>>>(x, Wq, bq, Wk, bk, Wv, bv);
    logits_kernel<<<dim3(T / 128, T / 128, BATCH), 256>>>();
    colstats_kernel<<<dim3(T / 32, BATCH, CHUNKS), dim3(32, 8)>>>();
    colmerge_kernel<<<M_TOT / 256, 256>>>();
    pv_kernel<<<dim3(C / 128, T / 128, BATCH), 256>>>(out);
    copyx_kernel<<<(M_TOT * 128) / 256, 256>>>(x, out);
}

// round 6
// speedup vs baseline: 3.0040x; 1.0080x over previous
#include <cuda_runtime.h>
#include <cstdint>

// Problem constants
constexpr int BATCH = 8;
constexpr int T = 2048;
constexpr int C = 512;                 // IN_CH = KEY = VAL = 512
constexpr int M_TOT = BATCH * T;       // 16384
constexpr int NCHUNK = 16;             // per-row-tile softmax partials
constexpr float SCALE = 0.044194173824159216f; // 1/sqrt(512)

constexpr int AK = 20;                 // padded k-stride for [m][k] smem tiles
constexpr int A_STG = 128 * AK;        // floats per A stage (2560)
constexpr int B_STG = 16 * 136;        // floats per B stage (2176)
constexpr int SMEM_AB  = 3 * (A_STG + B_STG) * 4;   // qkv / pv dynamic smem
constexpr int SMEM_AA  = 3 * (2 * A_STG) * 4;       // logits dynamic smem

// Scratch (device globals: allocation-free rule)
__device__ float g_q[M_TOT * C];       // pre-scaled by SCALE
__device__ float g_k[M_TOT * C];
__device__ float g_v[M_TOT * C];
__device__ float g_logits[(size_t)BATCH * T * T];
__device__ float g_pm[NCHUNK * M_TOT];
__device__ float g_pd[NCHUNK * M_TOT];
__device__ float g_cmax[M_TOT];
__device__ float g_cinv[M_TOT];

// ---------------------------------------------------------------------------
// helpers
// ---------------------------------------------------------------------------
__device__ __forceinline__ void mma_tf32(float d[4], const uint32_t a[4], const uint32_t b[2]) {
    asm volatile(
        "mma.sync.aligned.m16n8k8.row.col.f32.tf32.tf32.f32 "
        "{%0,%1,%2,%3}, {%4,%5,%6,%7}, {%8,%9}, {%0,%1,%2,%3};\n"
        : "+f"(d[0]), "+f"(d[1]), "+f"(d[2]), "+f"(d[3])
        : "r"(a[0]), "r"(a[1]), "r"(a[2]), "r"(a[3]), "r"(b[0]), "r"(b[1]));
}
__device__ __forceinline__ uint32_t smem_u32(const void* p) {
    return (uint32_t)__cvta_generic_to_shared(p);
}
#define CP16(dst, src) asm volatile("cp.async.ca.shared.global [%0], [%1], 16;" :: "r"(dst), "l"(src))
#define CP_COMMIT()    asm volatile("cp.async.commit_group;")
#define CP_WAIT(n)     asm volatile("cp.async.wait_group %0;" :: "n"(n))

// ---------------------------------------------------------------------------
// MMA consume: 128x128x16 tile. As is [128][AK] row-major (m,k).
// If BNK: Bs is [128][AK] (n,k); else [16][136] (k,n).
// Raw f32 bits fed to tf32 MMA (HW truncates mantissa).
// ---------------------------------------------------------------------------
template<bool BNK>
__device__ __forceinline__ void mma_consume(const float* __restrict__ As,
                                            const float* __restrict__ Bs,
                                            int mw, int nw, int r, int c,
                                            float acc[4][4][4])
{
#pragma unroll
    for (int ks = 0; ks < 2; ++ks) {
        const int kk = ks * 8;
        uint32_t af[4][4], bf[4][2];
#pragma unroll
        for (int mi = 0; mi < 4; ++mi) {
            const int m = mw + mi * 16 + r;
            af[mi][0] = __float_as_uint(As[m * AK + kk + c]);
            af[mi][1] = __float_as_uint(As[(m + 8) * AK + kk + c]);
            af[mi][2] = __float_as_uint(As[m * AK + kk + c + 4]);
            af[mi][3] = __float_as_uint(As[(m + 8) * AK + kk + c + 4]);
        }
#pragma unroll
        for (int ni = 0; ni < 4; ++ni) {
            const int n = nw + ni * 8 + r;
            if (BNK) {
                bf[ni][0] = __float_as_uint(Bs[n * AK + kk + c]);
                bf[ni][1] = __float_as_uint(Bs[n * AK + kk + c + 4]);
            } else {
                bf[ni][0] = __float_as_uint(Bs[(kk + c) * 136 + n]);
                bf[ni][1] = __float_as_uint(Bs[(kk + c + 4) * 136 + n]);
            }
        }
#pragma unroll
        for (int mi = 0; mi < 4; ++mi)
#pragma unroll
            for (int ni = 0; ni < 4; ++ni)
                mma_tf32(acc[mi][ni], af[mi], bf[ni]);
    }
}

// Fragment->global: acc[mi][ni][reg]:
//   row = rBase + mw + mi*16 + (lane>>2) + (reg>=2 ? 8 : 0)
//   col = cBase + nw + ni*8  + 2*(lane&3) + (reg&1)

// ---------------------------------------------------------------------------
// 1. QKV projection. 3-stage cp.async ring, one sync/iter.
//    Blocks (z==0, bx==0) additionally stream x into out[:, 0:512].
// ---------------------------------------------------------------------------
__global__ __launch_bounds__(256)
void qkv_kernel(const float* __restrict__ x,
                const float* __restrict__ Wq, const float* __restrict__ bq,
                const float* __restrict__ Wk, const float* __restrict__ bk,
                const float* __restrict__ Wv, const float* __restrict__ bv,
                float* __restrict__ xout)
{
    extern __shared__ float dsm[];
    float* As = dsm;                  // [3][A_STG]
    float* Bs = dsm + 3 * A_STG;      // [3][B_STG]

    const float* W; const float* bias; float* out; float oscale;
    if (blockIdx.z == 0)      { W = Wq; bias = bq; out = g_q; oscale = SCALE; }
    else if (blockIdx.z == 1) { W = Wk; bias = bk; out = g_k; oscale = 1.0f; }
    else                      { W = Wv; bias = bv; out = g_v; oscale = 1.0f; }

    const int rBase = blockIdx.y * 128;
    const int cBase = blockIdx.x * 128;
    const int tid = threadIdx.x, lane = tid & 31, warp = tid >> 5;
    const int mw = (warp >> 2) * 64, nw = (warp & 3) * 32;
    const int r = lane >> 2, cc = lane & 3;

    const int arow = tid >> 1, ahalf = (tid & 1) * 8;
    const int brow = tid >> 4, bseg = (tid & 15) * 8;
    const float* Asrc = x + (size_t)(rBase + arow) * C + ahalf;
    const float* Bsrc = W + (size_t)brow * C + cBase + bseg;
    uint32_t adst[3], bdst[3];
#pragma unroll
    for (int s = 0; s < 3; ++s) {
        adst[s] = smem_u32(&As[s * A_STG + arow * AK + ahalf]);
        bdst[s] = smem_u32(&Bs[s * B_STG + brow * 136 + bseg]);
    }

    auto issue = [&](int st, int k0) {
        CP16(adst[st],      Asrc + k0);
        CP16(adst[st] + 16, Asrc + k0 + 4);
        CP16(bdst[st],      Bsrc + (size_t)k0 * C);
        CP16(bdst[st] + 16, Bsrc + (size_t)k0 * C + 4);
        CP_COMMIT();
    };

    const bool wx = (blockIdx.z == 0) && (blockIdx.x == 0);
    float acc[4][4][4] = {};
    constexpr int NIT = C / 16;
    issue(0, 0);
    issue(1, 16);
    for (int it = 0; it < NIT; ++it) {
        if (it + 1 < NIT) CP_WAIT(1); else CP_WAIT(0);
        __syncthreads();
        const int st = it % 3;
        if (it + 2 < NIT) issue((it + 2) % 3, (it + 2) * 16);
        if (wx) {
            const float* a = &As[st * A_STG + arow * AK + ahalf];
            float4 v0 = *(const float4*)a;
            float4 v1 = *(const float4*)(a + 4);
            float* xo = xout + (size_t)(rBase + arow) * 1024 + it * 16 + ahalf;
            *(float4*)xo = v0;
            *(float4*)(xo + 4) = v1;
        }
        mma_consume<false>(&As[st * A_STG], &Bs[st * B_STG], mw, nw, r, cc, acc);
    }

#pragma unroll
    for (int mi = 0; mi < 4; ++mi) {
#pragma unroll
        for (int ni = 0; ni < 4; ++ni) {
            const int row = rBase + mw + mi * 16 + r;
            const int col = cBase + nw + ni * 8 + 2 * cc;
            float b0 = bias[col], b1 = bias[col + 1];
            float2 lo, hi;
            lo.x = (acc[mi][ni][0] + b0) * oscale;
            lo.y = (acc[mi][ni][1] + b1) * oscale;
            hi.x = (acc[mi][ni][2] + b0) * oscale;
            hi.y = (acc[mi][ni][3] + b1) * oscale;
            *(float2*)&out[(size_t)row * C + col]       = lo;
            *(float2*)&out[(size_t)(row + 8) * C + col] = hi;
        }
    }
}

// ---------------------------------------------------------------------------
// 2. logits = q . k^T (3-stage ring) + fused per-column partial softmax stats
//    (max, sum-exp over this tile's 128 rows, causally masked on diagonal),
//    written to g_pm/g_pd[chunk=by].
// ---------------------------------------------------------------------------
__global__ __launch_bounds__(256)
void logits_kernel()
{
    const int bx = blockIdx.x, by = blockIdx.y, b = blockIdx.z;
    if (bx > by) return;
    extern __shared__ float dsm[];
    float* As = dsm;                  // [3][A_STG]
    float* Bn = dsm + 3 * A_STG;      // [3][A_STG]
    __shared__ float ssm[8][32];
    __shared__ float ssd[8][32];

    const int rBase = by * 128;
    const int cBase = bx * 128;
    const float* A  = g_q + (size_t)b * T * C;
    const float* Bm = g_k + (size_t)b * T * C;
    float* Cp = g_logits + (size_t)b * T * T;

    const int tid = threadIdx.x, lane = tid & 31, warp = tid >> 5;
    const int mw = (warp >> 2) * 64, nw = (warp & 3) * 32;
    const int r = lane >> 2, cc = lane & 3;

    const int arow = tid >> 1, ahalf = (tid & 1) * 8;
    const float* Asrc = A  + (size_t)(rBase + arow) * C + ahalf;
    const float* Bsrc = Bm + (size_t)(cBase + arow) * C + ahalf;
    uint32_t adst[3], bdst[3];
#pragma unroll
    for (int s = 0; s < 3; ++s) {
        adst[s] = smem_u32(&As[s * A_STG + arow * AK + ahalf]);
        bdst[s] = smem_u32(&Bn[s * A_STG + arow * AK + ahalf]);
    }

    auto issue = [&](int st, int k0) {
        CP16(adst[st],      Asrc + k0);
        CP16(adst[st] + 16, Asrc + k0 + 4);
        CP16(bdst[st],      Bsrc + k0);
        CP16(bdst[st] + 16, Bsrc + k0 + 4);
        CP_COMMIT();
    };

    float acc[4][4][4] = {};
    constexpr int NIT = C / 16;
    issue(0, 0);
    issue(1, 16);
    for (int it = 0; it < NIT; ++it) {
        if (it + 1 < NIT) CP_WAIT(1); else CP_WAIT(0);
        __syncthreads();
        const int st = it % 3;
        if (it + 2 < NIT) issue((it + 2) % 3, (it + 2) * 16);
        mma_consume<true>(&As[st * A_STG], &Bn[st * A_STG], mw, nw, r, cc, acc);
    }

    // write logits tile
#pragma unroll
    for (int mi = 0; mi < 4; ++mi) {
#pragma unroll
        for (int ni = 0; ni < 4; ++ni) {
            const int row = rBase + mw + mi * 16 + r;
            const int col = cBase + nw + ni * 8 + 2 * cc;
            *(float2*)&Cp[(size_t)row * T + col]       = make_float2(acc[mi][ni][0], acc[mi][ni][1]);
            *(float2*)&Cp[(size_t)(row + 8) * T + col] = make_float2(acc[mi][ni][2], acc[mi][ni][3]);
        }
    }

    // fused per-column partial stats over this tile's 128 rows
    const bool diag = (bx == by);
    float mcol[8], dcol[8];
#pragma unroll
    for (int ni = 0; ni < 4; ++ni) {
#pragma unroll
        for (int sub = 0; sub < 2; ++sub) {
            const int j = ni * 2 + sub;
            const int sl = nw + ni * 8 + 2 * cc + sub;
            float m = -1e30f;
#pragma unroll
            for (int mi = 0; mi < 4; ++mi)
#pragma unroll
                for (int h = 0; h < 2; ++h) {
                    const int tl = mw + mi * 16 + r + h * 8;
                    const float v = acc[mi][ni][h * 2 + sub];
                    if ((!diag || tl >= sl) && v > m) m = v;
                }
            float d = 0.f;
#pragma unroll
            for (int mi = 0; mi < 4; ++mi)
#pragma unroll
                for (int h = 0; h < 2; ++h) {
                    const int tl = mw + mi * 16 + r + h * 8;
                    const float v = acc[mi][ni][h * 2 + sub];
                    if (!diag || tl >= sl) d += __expf(v - m);
                }
            // reduce over the 8 r-lanes (lane bits 2..4)
#pragma unroll
            for (int off = 4; off < 32; off <<= 1) {
                float m2 = __shfl_xor_sync(0xffffffffu, m, off);
                float d2 = __shfl_xor_sync(0xffffffffu, d, off);
                float nm = fmaxf(m, m2);
                d = d * __expf(m - nm) + d2 * __expf(m2 - nm);
                m = nm;
            }
            mcol[j] = m; dcol[j] = d;
        }
    }
    if (r == 0) {
#pragma unroll
        for (int j = 0; j < 8; ++j) {
            const int colw = (j >> 1) * 8 + 2 * cc + (j & 1);
            ssm[warp][colw] = mcol[j];
            ssd[warp][colw] = dcol[j];
        }
    }
    __syncthreads();
    if (warp < 4) {
        float m  = ssm[warp][lane],     d  = ssd[warp][lane];
        float m2 = ssm[warp + 4][lane], d2 = ssd[warp + 4][lane];
        float nm = fmaxf(m, m2);
        d = d * __expf(m - nm) + d2 * __expf(m2 - nm);
        const int colg = cBase + warp * 32 + lane;
        g_pm[(size_t)by * M_TOT + b * T + colg] = nm;
        g_pd[(size_t)by * M_TOT + b * T + colg] = d;
    }
}

// ---------------------------------------------------------------------------
// 3. Merge per-row-tile partials -> cmax, 1/sum (chunks ch >= s/128 only).
// ---------------------------------------------------------------------------
__global__ void colmerge_kernel()
{
    const int i = blockIdx.x * blockDim.x + threadIdx.x;
    const int s = i & (T - 1);
    float m = -1e30f, d = 0.f;
    for (int ch = s >> 7; ch < NCHUNK; ++ch) {
        float m2 = g_pm[(size_t)ch * M_TOT + i], d2 = g_pd[(size_t)ch * M_TOT + i];
        float nm = fmaxf(m, m2);
        d = d * __expf(m - nm) + d2 * __expf(m2 - nm);
        m = nm;
    }
    g_cmax[i] = m;
    g_cinv[i] = 1.0f / d;
}

// ---------------------------------------------------------------------------
// 4. read = softmax(logits) @ v. A path manual (exp/mask fused into STS),
//    B path cp.async; 3-stage ring, one sync/iter; k clamped (causal).
// ---------------------------------------------------------------------------
__global__ __launch_bounds__(256)
void pv_kernel(float* __restrict__ out)
{
    extern __shared__ float dsm[];
    float* As = dsm;                  // [3][A_STG]
    float* Bs = dsm + 3 * A_STG;      // [3][B_STG]

    const int b = blockIdx.z;
    const int rTile = (gridDim.y - 1) - blockIdx.y;   // heavy tiles first
    const int rBase = rTile * 128;
    const int cBase = blockIdx.x * 128;
    const float* A  = g_logits + (size_t)b * T * T;
    const float* Bm = g_v      + (size_t)b * T * C;
    const float* cm = g_cmax + b * T;
    const float* ci = g_cinv + b * T;

    const int tid = threadIdx.x, lane = tid & 31, warp = tid >> 5;
    const int mw = (warp >> 2) * 64, nw = (warp & 3) * 32;
    const int r = lane >> 2, cc = lane & 3;

    const int arow = tid >> 1, ahalf = (tid & 1) * 8;
    const int trow = rBase + arow;
    const int brow = tid >> 4, bseg = (tid & 15) * 8;
    const float* Asrc = A  + (size_t)trow * T + ahalf;
    const float* Bsrc = Bm + (size_t)brow * C + cBase + bseg;
    float* asw[3];
    uint32_t bdst[3];
#pragma unroll
    for (int s = 0; s < 3; ++s) {
        asw[s]  = &As[s * A_STG + arow * AK + ahalf];
        bdst[s] = smem_u32(&Bs[s * B_STG + brow * 136 + bseg]);
    }

    const int NIT = (rBase + 128) / 16;

    float4 pa0, pa1, pm0, pm1, pi0, pi1;
    auto loadA = [&](int k0) {
        pa0 = *(const float4*)(Asrc + k0);
        pa1 = *(const float4*)(Asrc + k0 + 4);
        pm0 = *(const float4*)&cm[k0 + ahalf];
        pm1 = *(const float4*)&cm[k0 + ahalf + 4];
        pi0 = *(const float4*)&ci[k0 + ahalf];
        pi1 = *(const float4*)&ci[k0 + ahalf + 4];
    };
    auto stsA = [&](int st, int k0) {
        float av[8] = {pa0.x, pa0.y, pa0.z, pa0.w, pa1.x, pa1.y, pa1.z, pa1.w};
        float mv[8] = {pm0.x, pm0.y, pm0.z, pm0.w, pm1.x, pm1.y, pm1.z, pm1.w};
        float iv[8] = {pi0.x, pi0.y, pi0.z, pi0.w, pi1.x, pi1.y, pi1.z, pi1.w};
        float p[8];
#pragma unroll
        for (int j = 0; j < 8; ++j) {
            const int s = k0 + ahalf + j;
            p[j] = (s <= trow) ? __expf(av[j] - mv[j]) * iv[j] : 0.0f;
        }
        *(float4*)(asw[st])     = make_float4(p[0], p[1], p[2], p[3]);
        *(float4*)(asw[st] + 4) = make_float4(p[4], p[5], p[6], p[7]);
    };
    auto issueB = [&](int st, int k0) {
        CP16(bdst[st],      Bsrc + (size_t)k0 * C);
        CP16(bdst[st] + 16, Bsrc + (size_t)k0 * C + 4);
        CP_COMMIT();
    };

    // prologue
    loadA(0);
    stsA(0, 0);
    loadA(16);
    issueB(0, 0);
    issueB(1, 16);

    float acc[4][4][4] = {};
    for (int it = 0; it < NIT; ++it) {
        if (it + 1 < NIT) CP_WAIT(1); else CP_WAIT(0);
        __syncthreads();
        if (it + 1 < NIT) stsA((it + 1) % 3, (it + 1) * 16);
        if (it + 2 < NIT) { loadA((it + 2) * 16); issueB((it + 2) % 3, (it + 2) * 16); }
        const int st = it % 3;
        mma_consume<false>(&As[st * A_STG], &Bs[st * B_STG], mw, nw, r, cc, acc);
    }

#pragma unroll
    for (int mi = 0; mi < 4; ++mi) {
#pragma unroll
        for (int ni = 0; ni < 4; ++ni) {
            const int row = rBase + mw + mi * 16 + r;
            const int col = cBase + nw + ni * 8 + 2 * cc;
            float* d0 = out + ((size_t)(b * T + row) * 1024) + 512 + col;
            float* d1 = out + ((size_t)(b * T + row + 8) * 1024) + 512 + col;
            *(float2*)d0 = make_float2(acc[mi][ni][0], acc[mi][ni][1]);
            *(float2*)d1 = make_float2(acc[mi][ni][2], acc[mi][ni][3]);
        }
    }
}

// ---------------------------------------------------------------------------
extern "C" void kernel_launch(void* const* d_in, const int* in_sizes, int n_in,
                              void* d_out, int out_size)
{
    const float* x  = (const float*)d_in[0];
    const float* Wq = (const float*)d_in[1];
    const float* bq = (const float*)d_in[2];
    const float* Wk = (const float*)d_in[3];
    const float* bk = (const float*)d_in[4];
    const float* Wv = (const float*)d_in[5];
    const float* bv = (const float*)d_in[6];
    float* out = (float*)d_out;

    cudaFuncSetAttribute(qkv_kernel,    cudaFuncAttributeMaxDynamicSharedMemorySize, SMEM_AB);
    cudaFuncSetAttribute(logits_kernel, cudaFuncAttributeMaxDynamicSharedMemorySize, SMEM_AA);
    cudaFuncSetAttribute(pv_kernel,     cudaFuncAttributeMaxDynamicSharedMemorySize, SMEM_AB);

    qkv_kernel<<<dim3(C / 128, M_TOT / 128, 3), 256, SMEM_AB>>>(x, Wq, bq, Wk, bk, Wv, bv, out);
    logits_kernel<<<dim3(T / 128, T / 128, BATCH), 256, SMEM_AA>>>();
    colmerge_kernel<<<M_TOT / 256, 256>>>();
    pv_kernel<<<dim3(C / 128, T / 128, BATCH), 256, SMEM_AB>>>(out);
}

// round 10
// speedup vs baseline: 3.1745x; 1.0568x over previous
#include <cuda_runtime.h>
#include <cstdint>

// Problem constants
constexpr int BATCH = 8;
constexpr int T = 2048;
constexpr int C = 512;                 // IN_CH = KEY = VAL = 512
constexpr int M_TOT = BATCH * T;       // 16384
constexpr int NCHUNK = 16;             // per-row-tile softmax partials
constexpr float SCALE = 0.044194173824159216f; // 1/sqrt(512)

constexpr int AK = 20;                 // padded k-stride for [m][k] smem tiles
constexpr int A_STG = 128 * AK;        // floats per A stage (2560)
constexpr int B_STG = 16 * 136;        // floats per B stage (2176)
constexpr int SMEM_AB  = 3 * (A_STG + B_STG) * 4;   // qkv / pv dynamic smem
constexpr int SMEM_AA  = 3 * (2 * A_STG) * 4;       // logits dynamic smem

// Scratch (device globals: allocation-free rule)
__device__ float g_q[M_TOT * C];       // pre-scaled by SCALE
__device__ float g_k[M_TOT * C];
__device__ float g_v[M_TOT * C];
__device__ float g_logits[(size_t)BATCH * T * T];
__device__ float g_pm[NCHUNK * M_TOT];
__device__ float g_pd[NCHUNK * M_TOT];
__device__ float g_cmax[M_TOT];
__device__ float g_cinv[M_TOT];

// ---------------------------------------------------------------------------
// helpers
// ---------------------------------------------------------------------------
__device__ __forceinline__ void mma_tf32(float d[4], const uint32_t a[4], const uint32_t b[2]) {
    asm volatile(
        "mma.sync.aligned.m16n8k8.row.col.f32.tf32.tf32.f32 "
        "{%0,%1,%2,%3}, {%4,%5,%6,%7}, {%8,%9}, {%0,%1,%2,%3};\n"
        : "+f"(d[0]), "+f"(d[1]), "+f"(d[2]), "+f"(d[3])
        : "r"(a[0]), "r"(a[1]), "r"(a[2]), "r"(a[3]), "r"(b[0]), "r"(b[1]));
}
__device__ __forceinline__ uint32_t smem_u32(const void* p) {
    return (uint32_t)__cvta_generic_to_shared(p);
}
__device__ __forceinline__ void ldsm4(uint32_t f[4], uint32_t addr) {
    asm volatile("ldmatrix.sync.aligned.m8n8.x4.shared.b16 {%0,%1,%2,%3}, [%4];"
                 : "=r"(f[0]), "=r"(f[1]), "=r"(f[2]), "=r"(f[3]) : "r"(addr));
}
#define CP16(dst, src) asm volatile("cp.async.ca.shared.global [%0], [%1], 16;" :: "r"(dst), "l"(src))
#define CP_COMMIT()    asm volatile("cp.async.commit_group;")
#define CP_WAIT(n)     asm volatile("cp.async.wait_group %0;" :: "n"(n))

// ---------------------------------------------------------------------------
// MMA consume: 128x128x16 tile.
// aAddr: smem addr of A stage base + per-lane ldmatrix offset (incl. mw).
// If BNK: bAddr likewise for [n][AK] B tile; else BsKN points at [16][136].
// ldmatrix.x4.b16 on b32 data: lane l gets element (row=l/4, col=l%4) of an
// 8x4-b32 matrix -> exactly the tf32 fragment ownership.
// ---------------------------------------------------------------------------
template<bool BNK>
__device__ __forceinline__ void mma_consume(uint32_t aAddr, uint32_t bAddr,
                                            const float* __restrict__ BsKN,
                                            int nw, int r, int c,
                                            float acc[4][4][4])
{
#pragma unroll
    for (int ks = 0; ks < 2; ++ks) {
        const int kkB = ks * 32;          // 8 floats -> 32 bytes
        uint32_t af[4][4], bf[4][2];
#pragma unroll
        for (int mi = 0; mi < 4; ++mi)
            ldsm4(af[mi], aAddr + mi * (16 * AK * 4) + kkB);
        if (BNK) {
#pragma unroll
            for (int p = 0; p < 2; ++p) {
                uint32_t t[4];
                ldsm4(t, bAddr + p * (16 * AK * 4) + kkB);
                bf[2 * p][0] = t[0]; bf[2 * p][1] = t[1];
                bf[2 * p + 1][0] = t[2]; bf[2 * p + 1][1] = t[3];
            }
        } else {
            const int kk = ks * 8;
#pragma unroll
            for (int ni = 0; ni < 4; ++ni) {
                const int n = nw + ni * 8 + r;
                bf[ni][0] = __float_as_uint(BsKN[(kk + c) * 136 + n]);
                bf[ni][1] = __float_as_uint(BsKN[(kk + c + 4) * 136 + n]);
            }
        }
#pragma unroll
        for (int mi = 0; mi < 4; ++mi)
#pragma unroll
            for (int ni = 0; ni < 4; ++ni)
                mma_tf32(acc[mi][ni], af[mi], bf[ni]);
    }
}

// Fragment->global: acc[mi][ni][reg]:
//   row = rBase + mw + mi*16 + (lane>>2) + (reg>=2 ? 8 : 0)
//   col = cBase + nw + ni*8  + 2*(lane&3) + (reg&1)

// ---------------------------------------------------------------------------
// 1. QKV projection. 3-stage cp.async ring, one sync/iter.
//    Blocks (z==0, bx==0) additionally stream x into out[:, 0:512].
// ---------------------------------------------------------------------------
__global__ __launch_bounds__(256, 2)
void qkv_kernel(const float* __restrict__ x,
                const float* __restrict__ Wq, const float* __restrict__ bq,
                const float* __restrict__ Wk, const float* __restrict__ bk,
                const float* __restrict__ Wv, const float* __restrict__ bv,
                float* __restrict__ xout)
{
    extern __shared__ float dsm[];
    float* As = dsm;                  // [3][A_STG]
    float* Bs = dsm + 3 * A_STG;      // [3][B_STG]

    const float* W; const float* bias; float* out; float oscale;
    if (blockIdx.z == 0)      { W = Wq; bias = bq; out = g_q; oscale = SCALE; }
    else if (blockIdx.z == 1) { W = Wk; bias = bk; out = g_k; oscale = 1.0f; }
    else                      { W = Wv; bias = bv; out = g_v; oscale = 1.0f; }

    const int rBase = blockIdx.y * 128;
    const int cBase = blockIdx.x * 128;
    const int tid = threadIdx.x, lane = tid & 31, warp = tid >> 5;
    const int mw = (warp >> 2) * 64, nw = (warp & 3) * 32;
    const int r = lane >> 2, cc = lane & 3;
    const int quad = lane >> 3, qi = lane & 7;
    const uint32_t aLane = ((mw + (quad & 1) * 8 + qi) * AK + (quad >> 1) * 4) * 4;

    const int arow = tid >> 1, ahalf = (tid & 1) * 8;
    const int brow = tid >> 4, bseg = (tid & 15) * 8;
    const float* Asrc = x + (size_t)(rBase + arow) * C + ahalf;
    const float* Bsrc = W + (size_t)brow * C + cBase + bseg;
    uint32_t adst[3], bdst[3], aAddrs[3];
#pragma unroll
    for (int s = 0; s < 3; ++s) {
        adst[s] = smem_u32(&As[s * A_STG + arow * AK + ahalf]);
        bdst[s] = smem_u32(&Bs[s * B_STG + brow * 136 + bseg]);
        aAddrs[s] = smem_u32(&As[s * A_STG]) + aLane;
    }

    auto issue = [&](int st, int k0) {
        CP16(adst[st],      Asrc + k0);
        CP16(adst[st] + 16, Asrc + k0 + 4);
        CP16(bdst[st],      Bsrc + (size_t)k0 * C);
        CP16(bdst[st] + 16, Bsrc + (size_t)k0 * C + 4);
        CP_COMMIT();
    };

    const bool wx = (blockIdx.z == 0) && (blockIdx.x == 0);
    float acc[4][4][4] = {};
    constexpr int NIT = C / 16;
    issue(0, 0);
    issue(1, 16);
    for (int it = 0; it < NIT; ++it) {
        if (it + 1 < NIT) CP_WAIT(1); else CP_WAIT(0);
        __syncthreads();
        const int st = it % 3;
        if (it + 2 < NIT) issue((it + 2) % 3, (it + 2) * 16);
        if (wx) {
            const float* a = &As[st * A_STG + arow * AK + ahalf];
            float4 v0 = *(const float4*)a;
            float4 v1 = *(const float4*)(a + 4);
            float* xo = xout + (size_t)(rBase + arow) * 1024 + it * 16 + ahalf;
            *(float4*)xo = v0;
            *(float4*)(xo + 4) = v1;
        }
        mma_consume<false>(aAddrs[st], 0, &Bs[st * B_STG], nw, r, cc, acc);
    }

#pragma unroll
    for (int mi = 0; mi < 4; ++mi) {
#pragma unroll
        for (int ni = 0; ni < 4; ++ni) {
            const int row = rBase + mw + mi * 16 + r;
            const int col = cBase + nw + ni * 8 + 2 * cc;
            float b0 = bias[col], b1 = bias[col + 1];
            float2 lo, hi;
            lo.x = (acc[mi][ni][0] + b0) * oscale;
            lo.y = (acc[mi][ni][1] + b1) * oscale;
            hi.x = (acc[mi][ni][2] + b0) * oscale;
            hi.y = (acc[mi][ni][3] + b1) * oscale;
            *(float2*)&out[(size_t)row * C + col]       = lo;
            *(float2*)&out[(size_t)(row + 8) * C + col] = hi;
        }
    }
}

// ---------------------------------------------------------------------------
// 2. logits = q . k^T (3-stage ring, ldmatrix both operands) + fused
//    per-column partial softmax stats written to g_pm/g_pd[chunk=by].
// ---------------------------------------------------------------------------
__global__ __launch_bounds__(256, 2)
void logits_kernel()
{
    const int bx = blockIdx.x, by = blockIdx.y, b = blockIdx.z;
    if (bx > by) return;
    extern __shared__ float dsm[];
    float* As = dsm;                  // [3][A_STG]
    float* Bn = dsm + 3 * A_STG;      // [3][A_STG]
    __shared__ float ssm[8][32];
    __shared__ float ssd[8][32];

    const int rBase = by * 128;
    const int cBase = bx * 128;
    const float* A  = g_q + (size_t)b * T * C;
    const float* Bm = g_k + (size_t)b * T * C;
    float* Cp = g_logits + (size_t)b * T * T;

    const int tid = threadIdx.x, lane = tid & 31, warp = tid >> 5;
    const int mw = (warp >> 2) * 64, nw = (warp & 3) * 32;
    const int r = lane >> 2, cc = lane & 3;
    const int quad = lane >> 3, qi = lane & 7;
    const uint32_t aLane = ((mw + (quad & 1) * 8 + qi) * AK + (quad >> 1) * 4) * 4;
    const uint32_t bLane = ((nw + (quad >> 1) * 8 + qi) * AK + (quad & 1) * 4) * 4;

    const int arow = tid >> 1, ahalf = (tid & 1) * 8;
    const float* Asrc = A  + (size_t)(rBase + arow) * C + ahalf;
    const float* Bsrc = Bm + (size_t)(cBase + arow) * C + ahalf;
    uint32_t adst[3], bdst[3], aAddrs[3], bAddrs[3];
#pragma unroll
    for (int s = 0; s < 3; ++s) {
        adst[s] = smem_u32(&As[s * A_STG + arow * AK + ahalf]);
        bdst[s] = smem_u32(&Bn[s * A_STG + arow * AK + ahalf]);
        aAddrs[s] = smem_u32(&As[s * A_STG]) + aLane;
        bAddrs[s] = smem_u32(&Bn[s * A_STG]) + bLane;
    }

    auto issue = [&](int st, int k0) {
        CP16(adst[st],      Asrc + k0);
        CP16(adst[st] + 16, Asrc + k0 + 4);
        CP16(bdst[st],      Bsrc + k0);
        CP16(bdst[st] + 16, Bsrc + k0 + 4);
        CP_COMMIT();
    };

    float acc[4][4][4] = {};
    constexpr int NIT = C / 16;
    issue(0, 0);
    issue(1, 16);
    for (int it = 0; it < NIT; ++it) {
        if (it + 1 < NIT) CP_WAIT(1); else CP_WAIT(0);
        __syncthreads();
        const int st = it % 3;
        if (it + 2 < NIT) issue((it + 2) % 3, (it + 2) * 16);
        mma_consume<true>(aAddrs[st], bAddrs[st], nullptr, nw, r, cc, acc);
    }

    // write logits tile
#pragma unroll
    for (int mi = 0; mi < 4; ++mi) {
#pragma unroll
        for (int ni = 0; ni < 4; ++ni) {
            const int row = rBase + mw + mi * 16 + r;
            const int col = cBase + nw + ni * 8 + 2 * cc;
            *(float2*)&Cp[(size_t)row * T + col]       = make_float2(acc[mi][ni][0], acc[mi][ni][1]);
            *(float2*)&Cp[(size_t)(row + 8) * T + col] = make_float2(acc[mi][ni][2], acc[mi][ni][3]);
        }
    }

    // fused per-column partial stats over this tile's 128 rows
    const bool diag = (bx == by);
    float mcol[8], dcol[8];
#pragma unroll
    for (int ni = 0; ni < 4; ++ni) {
#pragma unroll
        for (int sub = 0; sub < 2; ++sub) {
            const int j = ni * 2 + sub;
            const int sl = nw + ni * 8 + 2 * cc + sub;
            float m = -1e30f;
#pragma unroll
            for (int mi = 0; mi < 4; ++mi)
#pragma unroll
                for (int h = 0; h < 2; ++h) {
                    const int tl = mw + mi * 16 + r + h * 8;
                    const float v = acc[mi][ni][h * 2 + sub];
                    if ((!diag || tl >= sl) && v > m) m = v;
                }
            float d = 0.f;
#pragma unroll
            for (int mi = 0; mi < 4; ++mi)
#pragma unroll
                for (int h = 0; h < 2; ++h) {
                    const int tl = mw + mi * 16 + r + h * 8;
                    const float v = acc[mi][ni][h * 2 + sub];
                    if (!diag || tl >= sl) d += __expf(v - m);
                }
#pragma unroll
            for (int off = 4; off < 32; off <<= 1) {
                float m2 = __shfl_xor_sync(0xffffffffu, m, off);
                float d2 = __shfl_xor_sync(0xffffffffu, d, off);
                float nm = fmaxf(m, m2);
                d = d * __expf(m - nm) + d2 * __expf(m2 - nm);
                m = nm;
            }
            mcol[j] = m; dcol[j] = d;
        }
    }
    if (r == 0) {
#pragma unroll
        for (int j = 0; j < 8; ++j) {
            const int colw = (j >> 1) * 8 + 2 * cc + (j & 1);
            ssm[warp][colw] = mcol[j];
            ssd[warp][colw] = dcol[j];
        }
    }
    __syncthreads();
    if (warp < 4) {
        float m  = ssm[warp][lane],     d  = ssd[warp][lane];
        float m2 = ssm[warp + 4][lane], d2 = ssd[warp + 4][lane];
        float nm = fmaxf(m, m2);
        d = d * __expf(m - nm) + d2 * __expf(m2 - nm);
        const int colg = cBase + warp * 32 + lane;
        g_pm[(size_t)by * M_TOT + b * T + colg] = nm;
        g_pd[(size_t)by * M_TOT + b * T + colg] = d;
    }
}

// ---------------------------------------------------------------------------
// 3. Merge per-row-tile partials -> cmax, 1/sum (chunks ch >= s/128 only).
// ---------------------------------------------------------------------------
__global__ void colmerge_kernel()
{
    const int i = blockIdx.x * blockDim.x + threadIdx.x;
    const int s = i & (T - 1);
    float m = -1e30f, d = 0.f;
    for (int ch = s >> 7; ch < NCHUNK; ++ch) {
        float m2 = g_pm[(size_t)ch * M_TOT + i], d2 = g_pd[(size_t)ch * M_TOT + i];
        float nm = fmaxf(m, m2);
        d = d * __expf(m - nm) + d2 * __expf(m2 - nm);
        m = nm;
    }
    g_cmax[i] = m;
    g_cinv[i] = 1.0f / d;
}

// ---------------------------------------------------------------------------
// 4. read = softmax(logits) @ v. A path manual (exp/mask fused into STS),
//    B path cp.async; 3-stage ring, one sync/iter; k clamped (causal).
// ---------------------------------------------------------------------------
__global__ __launch_bounds__(256, 2)
void pv_kernel(float* __restrict__ out)
{
    extern __shared__ float dsm[];
    float* As = dsm;                  // [3][A_STG]
    float* Bs = dsm + 3 * A_STG;      // [3][B_STG]

    const int b = blockIdx.z;
    const int rTile = (gridDim.y - 1) - blockIdx.y;   // heavy tiles first
    const int rBase = rTile * 128;
    const int cBase = blockIdx.x * 128;
    const float* A  = g_logits + (size_t)b * T * T;
    const float* Bm = g_v      + (size_t)b * T * C;
    const float* cm = g_cmax + b * T;
    const float* ci = g_cinv + b * T;

    const int tid = threadIdx.x, lane = tid & 31, warp = tid >> 5;
    const int mw = (warp >> 2) * 64, nw = (warp & 3) * 32;
    const int r = lane >> 2, cc = lane & 3;
    const int quad = lane >> 3, qi = lane & 7;
    const uint32_t aLane = ((mw + (quad & 1) * 8 + qi) * AK + (quad >> 1) * 4) * 4;

    const int arow = tid >> 1, ahalf = (tid & 1) * 8;
    const int trow = rBase + arow;
    const int brow = tid >> 4, bseg = (tid & 15) * 8;
    const float* Asrc = A  + (size_t)trow * T + ahalf;
    const float* Bsrc = Bm + (size_t)brow * C + cBase + bseg;
    float* asw[3];
    uint32_t bdst[3], aAddrs[3];
#pragma unroll
    for (int s = 0; s < 3; ++s) {
        asw[s]  = &As[s * A_STG + arow * AK + ahalf];
        bdst[s] = smem_u32(&Bs[s * B_STG + brow * 136 + bseg]);
        aAddrs[s] = smem_u32(&As[s * A_STG]) + aLane;
    }

    const int NIT = (rBase + 128) / 16;

    float4 pa0, pa1, pm0, pm1, pi0, pi1;
    auto loadA = [&](int k0) {
        pa0 = *(const float4*)(Asrc + k0);
        pa1 = *(const float4*)(Asrc + k0 + 4);
        pm0 = *(const float4*)&cm[k0 + ahalf];
        pm1 = *(const float4*)&cm[k0 + ahalf + 4];
        pi0 = *(const float4*)&ci[k0 + ahalf];
        pi1 = *(const float4*)&ci[k0 + ahalf + 4];
    };
    auto stsA = [&](int st, int k0) {
        float av[8] = {pa0.x, pa0.y, pa0.z, pa0.w, pa1.x, pa1.y, pa1.z, pa1.w};
        float mv[8] = {pm0.x, pm0.y, pm0.z, pm0.w, pm1.x, pm1.y, pm1.z, pm1.w};
        float iv[8] = {pi0.x, pi0.y, pi0.z, pi0.w, pi1.x, pi1.y, pi1.z, pi1.w};
        float p[8];
#pragma unroll
        for (int j = 0; j < 8; ++j) {
            const int s = k0 + ahalf + j;
            p[j] = (s <= trow) ? __expf(av[j] - mv[j]) * iv[j] : 0.0f;
        }
        *(float4*)(asw[st])     = make_float4(p[0], p[1], p[2], p[3]);
        *(float4*)(asw[st] + 4) = make_float4(p[4], p[5], p[6], p[7]);
    };
    auto issueB = [&](int st, int k0) {
        CP16(bdst[st],      Bsrc + (size_t)k0 * C);
        CP16(bdst[st] + 16, Bsrc + (size_t)k0 * C + 4);
        CP_COMMIT();
    };

    // prologue
    loadA(0);
    stsA(0, 0);
    loadA(16);
    issueB(0, 0);
    issueB(1, 16);

    float acc[4][4][4] = {};
    for (int it = 0; it < NIT; ++it) {
        if (it + 1 < NIT) CP_WAIT(1); else CP_WAIT(0);
        __syncthreads();
        if (it + 1 < NIT) stsA((it + 1) % 3, (it + 1) * 16);
        if (it + 2 < NIT) { loadA((it + 2) * 16); issueB((it + 2) % 3, (it + 2) * 16); }
        const int st = it % 3;
        mma_consume<false>(aAddrs[st], 0, &Bs[st * B_STG], nw, r, cc, acc);
    }

#pragma unroll
    for (int mi = 0; mi < 4; ++mi) {
#pragma unroll
        for (int ni = 0; ni < 4; ++ni) {
            const int row = rBase + mw + mi * 16 + r;
            const int col = cBase + nw + ni * 8 + 2 * cc;
            float* d0 = out + ((size_t)(b * T + row) * 1024) + 512 + col;
            float* d1 = out + ((size_t)(b * T + row + 8) * 1024) + 512 + col;
            *(float2*)d0 = make_float2(acc[mi][ni][0], acc[mi][ni][1]);
            *(float2*)d1 = make_float2(acc[mi][ni][2], acc[mi][ni][3]);
        }
    }
}

// ---------------------------------------------------------------------------
extern "C" void kernel_launch(void* const* d_in, const int* in_sizes, int n_in,
                              void* d_out, int out_size)
{
    const float* x  = (const float*)d_in[0];
    const float* Wq = (const float*)d_in[1];
    const float* bq = (const float*)d_in[2];
    const float* Wk = (const float*)d_in[3];
    const float* bk = (const float*)d_in[4];
    const float* Wv = (const float*)d_in[5];
    const float* bv = (const float*)d_in[6];
    float* out = (float*)d_out;

    cudaFuncSetAttribute(qkv_kernel,    cudaFuncAttributeMaxDynamicSharedMemorySize, SMEM_AB);
    cudaFuncSetAttribute(logits_kernel, cudaFuncAttributeMaxDynamicSharedMemorySize, SMEM_AA);
    cudaFuncSetAttribute(pv_kernel,     cudaFuncAttributeMaxDynamicSharedMemorySize, SMEM_AB);

    qkv_kernel<<<dim3(C / 128, M_TOT / 128, 3), 256, SMEM_AB>>>(x, Wq, bq, Wk, bk, Wv, bv, out);
    logits_kernel<<<dim3(T / 128, T / 128, BATCH), 256, SMEM_AA>>>();
    colmerge_kernel<<<M_TOT / 256, 256>>>();
    pv_kernel<<<dim3(C / 128, T / 128, BATCH), 256, SMEM_AB>>>(out);
}

// round 13
// speedup vs baseline: 3.3189x; 1.0455x over previous
#include <cuda_runtime.h>
#include <cstdint>

// Problem constants
constexpr int BATCH = 8;
constexpr int T = 2048;
constexpr int C = 512;                 // IN_CH = KEY = VAL = 512
constexpr int M_TOT = BATCH * T;       // 16384
constexpr int NCHUNK = 32;             // per-64-row-segment softmax partials
constexpr float SCALE = 0.044194173824159216f; // 1/sqrt(512)

constexpr int AK = 20;                 // padded k-stride for [m][k] smem tiles
constexpr int A_STG = 128 * AK;        // floats per A stage (2560)
constexpr int B_STG = 16 * 136;        // floats per B stage (2176)
constexpr int SMEM_AB  = 3 * (A_STG + B_STG) * 4;   // qkv / pv dynamic smem
constexpr int SMEM_AA  = 3 * (2 * A_STG) * 4;       // logits dynamic smem

// Scratch (device globals: allocation-free rule)
__device__ float g_q[M_TOT * C];       // pre-scaled by SCALE
__device__ float g_k[M_TOT * C];
__device__ float g_v[M_TOT * C];
__device__ float g_logits[(size_t)BATCH * T * T];   // exp(l - m_seg), 0 above diag
__device__ float g_pm[(size_t)NCHUNK * M_TOT];      // partial max -> then rescale factor f
__device__ float g_pd[(size_t)NCHUNK * M_TOT];      // partial denom

// ---------------------------------------------------------------------------
// helpers
// ---------------------------------------------------------------------------
__device__ __forceinline__ void mma_tf32(float d[4], const uint32_t a[4], const uint32_t b[2]) {
    asm volatile(
        "mma.sync.aligned.m16n8k8.row.col.f32.tf32.tf32.f32 "
        "{%0,%1,%2,%3}, {%4,%5,%6,%7}, {%8,%9}, {%0,%1,%2,%3};\n"
        : "+f"(d[0]), "+f"(d[1]), "+f"(d[2]), "+f"(d[3])
        : "r"(a[0]), "r"(a[1]), "r"(a[2]), "r"(a[3]), "r"(b[0]), "r"(b[1]));
}
__device__ __forceinline__ uint32_t smem_u32(const void* p) {
    return (uint32_t)__cvta_generic_to_shared(p);
}
__device__ __forceinline__ void ldsm4(uint32_t f[4], uint32_t addr) {
    asm volatile("ldmatrix.sync.aligned.m8n8.x4.shared.b16 {%0,%1,%2,%3}, [%4];"
                 : "=r"(f[0]), "=r"(f[1]), "=r"(f[2]), "=r"(f[3]) : "r"(addr));
}
#define CP16(dst, src) asm volatile("cp.async.ca.shared.global [%0], [%1], 16;" :: "r"(dst), "l"(src))
#define CP_COMMIT()    asm volatile("cp.async.commit_group;")
#define CP_WAIT(n)     asm volatile("cp.async.wait_group %0;" :: "n"(n))

// ---------------------------------------------------------------------------
// MMA consume: 128x128x16 tile.
// aAddr: smem addr of A stage base + per-lane ldmatrix offset (incl. mw).
// If BNK: bAddr likewise for [n][AK] B tile; else BsKN points at [16][136].
// ---------------------------------------------------------------------------
template<bool BNK>
__device__ __forceinline__ void mma_consume(uint32_t aAddr, uint32_t bAddr,
                                            const float* __restrict__ BsKN,
                                            int nw, int r, int c,
                                            float acc[4][4][4])
{
#pragma unroll
    for (int ks = 0; ks < 2; ++ks) {
        const int kkB = ks * 32;          // 8 floats -> 32 bytes
        uint32_t af[4][4], bf[4][2];
#pragma unroll
        for (int mi = 0; mi < 4; ++mi)
            ldsm4(af[mi], aAddr + mi * (16 * AK * 4) + kkB);
        if (BNK) {
#pragma unroll
            for (int p = 0; p < 2; ++p) {
                uint32_t t[4];
                ldsm4(t, bAddr + p * (16 * AK * 4) + kkB);
                bf[2 * p][0] = t[0]; bf[2 * p][1] = t[1];
                bf[2 * p + 1][0] = t[2]; bf[2 * p + 1][1] = t[3];
            }
        } else {
            const int kk = ks * 8;
#pragma unroll
            for (int ni = 0; ni < 4; ++ni) {
                const int n = nw + ni * 8 + r;
                bf[ni][0] = __float_as_uint(BsKN[(kk + c) * 136 + n]);
                bf[ni][1] = __float_as_uint(BsKN[(kk + c + 4) * 136 + n]);
            }
        }
#pragma unroll
        for (int mi = 0; mi < 4; ++mi)
#pragma unroll
            for (int ni = 0; ni < 4; ++ni)
                mma_tf32(acc[mi][ni], af[mi], bf[ni]);
    }
}

// Fragment->global: acc[mi][ni][reg]:
//   row = rBase + mw + mi*16 + (lane>>2) + (reg>=2 ? 8 : 0)
//   col = cBase + nw + ni*8  + 2*(lane&3) + (reg&1)

// ---------------------------------------------------------------------------
// 1. QKV projection. 3-stage cp.async ring, one sync/iter.
//    Blocks (z==0, bx==0) additionally stream x into out[:, 0:512].
// ---------------------------------------------------------------------------
__global__ __launch_bounds__(256, 2)
void qkv_kernel(const float* __restrict__ x,
                const float* __restrict__ Wq, const float* __restrict__ bq,
                const float* __restrict__ Wk, const float* __restrict__ bk,
                const float* __restrict__ Wv, const float* __restrict__ bv,
                float* __restrict__ xout)
{
    extern __shared__ float dsm[];
    float* As = dsm;                  // [3][A_STG]
    float* Bs = dsm + 3 * A_STG;      // [3][B_STG]

    const float* W; const float* bias; float* out; float oscale;
    if (blockIdx.z == 0)      { W = Wq; bias = bq; out = g_q; oscale = SCALE; }
    else if (blockIdx.z == 1) { W = Wk; bias = bk; out = g_k; oscale = 1.0f; }
    else                      { W = Wv; bias = bv; out = g_v; oscale = 1.0f; }

    const int rBase = blockIdx.y * 128;
    const int cBase = blockIdx.x * 128;
    const int tid = threadIdx.x, lane = tid & 31, warp = tid >> 5;
    const int mw = (warp >> 2) * 64, nw = (warp & 3) * 32;
    const int r = lane >> 2, cc = lane & 3;
    const int quad = lane >> 3, qi = lane & 7;
    const uint32_t aLane = ((mw + (quad & 1) * 8 + qi) * AK + (quad >> 1) * 4) * 4;

    const int arow = tid >> 1, ahalf = (tid & 1) * 8;
    const int brow = tid >> 4, bseg = (tid & 15) * 8;
    const float* Asrc = x + (size_t)(rBase + arow) * C + ahalf;
    const float* Bsrc = W + (size_t)brow * C + cBase + bseg;
    uint32_t adst[3], bdst[3], aAddrs[3];
#pragma unroll
    for (int s = 0; s < 3; ++s) {
        adst[s] = smem_u32(&As[s * A_STG + arow * AK + ahalf]);
        bdst[s] = smem_u32(&Bs[s * B_STG + brow * 136 + bseg]);
        aAddrs[s] = smem_u32(&As[s * A_STG]) + aLane;
    }

    auto issue = [&](int st, int k0) {
        CP16(adst[st],      Asrc + k0);
        CP16(adst[st] + 16, Asrc + k0 + 4);
        CP16(bdst[st],      Bsrc + (size_t)k0 * C);
        CP16(bdst[st] + 16, Bsrc + (size_t)k0 * C + 4);
        CP_COMMIT();
    };

    const bool wx = (blockIdx.z == 0) && (blockIdx.x == 0);
    float acc[4][4][4] = {};
    constexpr int NIT = C / 16;
    issue(0, 0);
    issue(1, 16);
    for (int it = 0; it < NIT; ++it) {
        if (it + 1 < NIT) CP_WAIT(1); else CP_WAIT(0);
        __syncthreads();
        const int st = it % 3;
        if (it + 2 < NIT) issue((it + 2) % 3, (it + 2) * 16);
        if (wx) {
            const float* a = &As[st * A_STG + arow * AK + ahalf];
            float4 v0 = *(const float4*)a;
            float4 v1 = *(const float4*)(a + 4);
            float* xo = xout + (size_t)(rBase + arow) * 1024 + it * 16 + ahalf;
            *(float4*)xo = v0;
            *(float4*)(xo + 4) = v1;
        }
        mma_consume<false>(aAddrs[st], 0, &Bs[st * B_STG], nw, r, cc, acc);
    }

#pragma unroll
    for (int mi = 0; mi < 4; ++mi) {
#pragma unroll
        for (int ni = 0; ni < 4; ++ni) {
            const int row = rBase + mw + mi * 16 + r;
            const int col = cBase + nw + ni * 8 + 2 * cc;
            float b0 = bias[col], b1 = bias[col + 1];
            float2 lo, hi;
            lo.x = (acc[mi][ni][0] + b0) * oscale;
            lo.y = (acc[mi][ni][1] + b1) * oscale;
            hi.x = (acc[mi][ni][2] + b0) * oscale;
            hi.y = (acc[mi][ni][3] + b1) * oscale;
            *(float2*)&out[(size_t)row * C + col]       = lo;
            *(float2*)&out[(size_t)(row + 8) * C + col] = hi;
        }
    }
}

// ---------------------------------------------------------------------------
// 2. logits = q . k^T (3-stage ring, ldmatrix both operands).
//    Per-warp 64-row column-segment softmax: m_seg via 3 shfls, then the
//    tile is stored as exp(l - m_seg) (0 above diag); (m_seg, sum) partials
//    written to g_pm/g_pd[chunk = 2*by + (mw?1:0)].
// ---------------------------------------------------------------------------
__global__ __launch_bounds__(256, 2)
void logits_kernel()
{
    const int bx = blockIdx.x, by = blockIdx.y, b = blockIdx.z;
    if (bx > by) return;
    extern __shared__ float dsm[];
    float* As = dsm;                  // [3][A_STG]
    float* Bn = dsm + 3 * A_STG;      // [3][A_STG]

    const int rBase = by * 128;
    const int cBase = bx * 128;
    const float* A  = g_q + (size_t)b * T * C;
    const float* Bm = g_k + (size_t)b * T * C;
    float* Cp = g_logits + (size_t)b * T * T;

    const int tid = threadIdx.x, lane = tid & 31, warp = tid >> 5;
    const int mw = (warp >> 2) * 64, nw = (warp & 3) * 32;
    const int r = lane >> 2, cc = lane & 3;
    const int quad = lane >> 3, qi = lane & 7;
    const uint32_t aLane = ((mw + (quad & 1) * 8 + qi) * AK + (quad >> 1) * 4) * 4;
    const uint32_t bLane = ((nw + (quad >> 1) * 8 + qi) * AK + (quad & 1) * 4) * 4;

    const int arow = tid >> 1, ahalf = (tid & 1) * 8;
    const float* Asrc = A  + (size_t)(rBase + arow) * C + ahalf;
    const float* Bsrc = Bm + (size_t)(cBase + arow) * C + ahalf;
    uint32_t adst[3], bdst[3], aAddrs[3], bAddrs[3];
#pragma unroll
    for (int s = 0; s < 3; ++s) {
        adst[s] = smem_u32(&As[s * A_STG + arow * AK + ahalf]);
        bdst[s] = smem_u32(&Bn[s * A_STG + arow * AK + ahalf]);
        aAddrs[s] = smem_u32(&As[s * A_STG]) + aLane;
        bAddrs[s] = smem_u32(&Bn[s * A_STG]) + bLane;
    }

    auto issue = [&](int st, int k0) {
        CP16(adst[st],      Asrc + k0);
        CP16(adst[st] + 16, Asrc + k0 + 4);
        CP16(bdst[st],      Bsrc + k0);
        CP16(bdst[st] + 16, Bsrc + k0 + 4);
        CP_COMMIT();
    };

    float acc[4][4][4] = {};
    constexpr int NIT = C / 16;
    issue(0, 0);
    issue(1, 16);
    for (int it = 0; it < NIT; ++it) {
        if (it + 1 < NIT) CP_WAIT(1); else CP_WAIT(0);
        __syncthreads();
        const int st = it % 3;
        if (it + 2 < NIT) issue((it + 2) % 3, (it + 2) * 16);
        mma_consume<true>(aAddrs[st], bAddrs[st], nullptr, nw, r, cc, acc);
    }

    // per-warp 64-row column-segment stats; acc -> exp(v - m_seg) in place
    const bool diag = (bx == by);
    float mcol[8], dcol[8];
#pragma unroll
    for (int ni = 0; ni < 4; ++ni) {
#pragma unroll
        for (int sub = 0; sub < 2; ++sub) {
            const int j = ni * 2 + sub;
            const int sl = nw + ni * 8 + 2 * cc + sub;   // column within tile
            float m = -1e30f;
#pragma unroll
            for (int mi = 0; mi < 4; ++mi)
#pragma unroll
                for (int h = 0; h < 2; ++h) {
                    const int tl = mw + mi * 16 + r + h * 8;
                    const float v = acc[mi][ni][h * 2 + sub];
                    if ((!diag || tl >= sl) && v > m) m = v;
                }
#pragma unroll
            for (int off = 4; off < 32; off <<= 1)
                m = fmaxf(m, __shfl_xor_sync(0xffffffffu, m, off));
            float d = 0.f;
#pragma unroll
            for (int mi = 0; mi < 4; ++mi)
#pragma unroll
                for (int h = 0; h < 2; ++h) {
                    const int tl = mw + mi * 16 + r + h * 8;
                    const float v = acc[mi][ni][h * 2 + sub];
                    const float p = (!diag || tl >= sl) ? __expf(v - m) : 0.0f;
                    acc[mi][ni][h * 2 + sub] = p;
                    d += p;
                }
#pragma unroll
            for (int off = 4; off < 32; off <<= 1)
                d += __shfl_xor_sync(0xffffffffu, d, off);
            mcol[j] = m; dcol[j] = d;
        }
    }

    // write p-hat tile
#pragma unroll
    for (int mi = 0; mi < 4; ++mi) {
#pragma unroll
        for (int ni = 0; ni < 4; ++ni) {
            const int row = rBase + mw + mi * 16 + r;
            const int col = cBase + nw + ni * 8 + 2 * cc;
            *(float2*)&Cp[(size_t)row * T + col]       = make_float2(acc[mi][ni][0], acc[mi][ni][1]);
            *(float2*)&Cp[(size_t)(row + 8) * T + col] = make_float2(acc[mi][ni][2], acc[mi][ni][3]);
        }
    }

    // write segment partials (chunk = 64-row granularity)
    if (r == 0) {
        const int chw = 2 * by + (mw >> 6);
#pragma unroll
        for (int j = 0; j < 8; ++j) {
            const int colg = cBase + nw + (j >> 1) * 8 + 2 * cc + (j & 1);
            g_pm[(size_t)chw * M_TOT + b * T + colg] = mcol[j];
            g_pd[(size_t)chw * M_TOT + b * T + colg] = dcol[j];
        }
    }
}

// ---------------------------------------------------------------------------
// 3. Merge segment partials; overwrite g_pm with rescale factors
//    f[ch][s] = exp(m_seg - cmax) / sum. Boundary chunk (fully masked) = 0.
// ---------------------------------------------------------------------------
__global__ void colmerge_kernel()
{
    const int i = blockIdx.x * blockDim.x + threadIdx.x;
    const int s = i & (T - 1);
    const int ch0 = s >> 6;
    float m = -1e30f, d = 0.f;
    for (int ch = ch0; ch < NCHUNK; ++ch) {
        float m2 = g_pm[(size_t)ch * M_TOT + i], d2 = g_pd[(size_t)ch * M_TOT + i];
        float nm = fmaxf(m, m2);
        d = d * __expf(m - nm) + d2 * __expf(m2 - nm);
        m = nm;
    }
    const float inv = 1.0f / d;
    for (int ch = ch0; ch < NCHUNK; ++ch) {
        float m2 = g_pm[(size_t)ch * M_TOT + i];
        g_pm[(size_t)ch * M_TOT + i] = __expf(m2 - m) * inv;
    }
    if (ch0 > 0) g_pm[(size_t)(ch0 - 1) * M_TOT + i] = 0.0f;  // read by pv, fully masked
}

// ---------------------------------------------------------------------------
// 4. read = P @ v. A path: stored p-hat * f (single FMUL, no exp, no mask);
//    B path cp.async; 3-stage ring, one sync/iter; k clamped (causal).
// ---------------------------------------------------------------------------
__global__ __launch_bounds__(256, 2)
void pv_kernel(float* __restrict__ out)
{
    extern __shared__ float dsm[];
    float* As = dsm;                  // [3][A_STG]
    float* Bs = dsm + 3 * A_STG;      // [3][B_STG]

    const int b = blockIdx.z;
    const int rTile = (gridDim.y - 1) - blockIdx.y;   // heavy tiles first
    const int rBase = rTile * 128;
    const int cBase = blockIdx.x * 128;
    const float* A  = g_logits + (size_t)b * T * T;
    const float* Bm = g_v      + (size_t)b * T * C;

    const int tid = threadIdx.x, lane = tid & 31, warp = tid >> 5;
    const int mw = (warp >> 2) * 64, nw = (warp & 3) * 32;
    const int r = lane >> 2, cc = lane & 3;
    const int quad = lane >> 3, qi = lane & 7;
    const uint32_t aLane = ((mw + (quad & 1) * 8 + qi) * AK + (quad >> 1) * 4) * 4;

    const int arow = tid >> 1, ahalf = (tid & 1) * 8;
    const int trow = rBase + arow;
    const int brow = tid >> 4, bseg = (tid & 15) * 8;
    const float* Asrc = A  + (size_t)trow * T + ahalf;
    const float* Bsrc = Bm + (size_t)brow * C + cBase + bseg;
    const float* Fsrc = g_pm + (size_t)(trow >> 6) * M_TOT + b * T + ahalf;  // rescale stream
    float* asw[3];
    uint32_t bdst[3], aAddrs[3];
#pragma unroll
    for (int s = 0; s < 3; ++s) {
        asw[s]  = &As[s * A_STG + arow * AK + ahalf];
        bdst[s] = smem_u32(&Bs[s * B_STG + brow * 136 + bseg]);
        aAddrs[s] = smem_u32(&As[s * A_STG]) + aLane;
    }

    const int NIT = (rBase + 128) / 16;

    float4 pa0, pa1, pf0, pf1;
    auto loadA = [&](int k0) {
        pa0 = *(const float4*)(Asrc + k0);
        pa1 = *(const float4*)(Asrc + k0 + 4);
        pf0 = *(const float4*)(Fsrc + k0);
        pf1 = *(const float4*)(Fsrc + k0 + 4);
    };
    auto stsA = [&](int st) {
        float4 q0, q1;
        q0.x = pa0.x * pf0.x; q0.y = pa0.y * pf0.y;
        q0.z = pa0.z * pf0.z; q0.w = pa0.w * pf0.w;
        q1.x = pa1.x * pf1.x; q1.y = pa1.y * pf1.y;
        q1.z = pa1.z * pf1.z; q1.w = pa1.w * pf1.w;
        *(float4*)(asw[st])     = q0;
        *(float4*)(asw[st] + 4) = q1;
    };
    auto issueB = [&](int st, int k0) {
        CP16(bdst[st],      Bsrc + (size_t)k0 * C);
        CP16(bdst[st] + 16, Bsrc + (size_t)k0 * C + 4);
        CP_COMMIT();
    };

    // prologue
    loadA(0);
    stsA(0);
    loadA(16);
    issueB(0, 0);
    issueB(1, 16);

    float acc[4][4][4] = {};
    for (int it = 0; it < NIT; ++it) {
        if (it + 1 < NIT) CP_WAIT(1); else CP_WAIT(0);
        __syncthreads();
        if (it + 1 < NIT) stsA((it + 1) % 3);
        if (it + 2 < NIT) { loadA((it + 2) * 16); issueB((it + 2) % 3, (it + 2) * 16); }
        const int st = it % 3;
        mma_consume<false>(aAddrs[st], 0, &Bs[st * B_STG], nw, r, cc, acc);
    }

#pragma unroll
    for (int mi = 0; mi < 4; ++mi) {
#pragma unroll
        for (int ni = 0; ni < 4; ++ni) {
            const int row = rBase + mw + mi * 16 + r;
            const int col = cBase + nw + ni * 8 + 2 * cc;
            float* d0 = out + ((size_t)(b * T + row) * 1024) + 512 + col;
            float* d1 = out + ((size_t)(b * T + row + 8) * 1024) + 512 + col;
            *(float2*)d0 = make_float2(acc[mi][ni][0], acc[mi][ni][1]);
            *(float2*)d1 = make_float2(acc[mi][ni][2], acc[mi][ni][3]);
        }
    }
}

// ---------------------------------------------------------------------------
extern "C" void kernel_launch(void* const* d_in, const int* in_sizes, int n_in,
                              void* d_out, int out_size)
{
    const float* x  = (const float*)d_in[0];
    const float* Wq = (const float*)d_in[1];
    const float* bq = (const float*)d_in[2];
    const float* Wk = (const float*)d_in[3];
    const float* bk = (const float*)d_in[4];
    const float* Wv = (const float*)d_in[5];
    const float* bv = (const float*)d_in[6];
    float* out = (float*)d_out;

    cudaFuncSetAttribute(qkv_kernel,    cudaFuncAttributeMaxDynamicSharedMemorySize, SMEM_AB);
    cudaFuncSetAttribute(logits_kernel, cudaFuncAttributeMaxDynamicSharedMemorySize, SMEM_AA);
    cudaFuncSetAttribute(pv_kernel,     cudaFuncAttributeMaxDynamicSharedMemorySize, SMEM_AB);

    qkv_kernel<<<dim3(C / 128, M_TOT / 128, 3), 256, SMEM_AB>>>(x, Wq, bq, Wk, bk, Wv, bv, out);
    logits_kernel<<<dim3(T / 128, T / 128, BATCH), 256, SMEM_AA>>>();
    colmerge_kernel<<<M_TOT / 256, 256>>>();
    pv_kernel<<<dim3(C / 128, T / 128, BATCH), 256, SMEM_AB>>>(out);
}